// round 14
// baseline (speedup 1.0000x reference)
#include <cuda_runtime.h>
#include <cuda_bf16.h>
#include <cstdint>

#define BATCH   16
#define SEQ     512
#define DIM     128
#define HID     1024
#define NLAYER  6
#define NHEAD   16
#define HEADDIM 64
#define AHID    2730
#define APAD    2736
#define NTOK    8192
#define RSCALE  0.4082482904638630f
#define RMSEPS  1e-6f

#define SPITCH  40                // GEMM smem pitch (80B, conflict-free)

// ---------------------------------------------------------------------------
// Device scratch (allocation-free)
// ---------------------------------------------------------------------------
__device__ __nv_bfloat16 g_winh[131072],       g_winl[131072];
__device__ __nv_bfloat16 g_wqkvh[6*3145728],   g_wqkvl[6*3145728];   // [3072][1024]
__device__ __nv_bfloat16 g_woh [6*1048576],    g_wol [6*1048576];
__device__ __nv_bfloat16 g_w13h[6*5591040],    g_w13l[6*5591040];    // [5460][1024] interleaved w1/w3
__device__ __nv_bfloat16 g_w2h [6*1024*APAD],  g_w2l [6*1024*APAD];  // [1024][APAD]
__device__ __nv_bfloat16 g_outwh[131072],      g_outwl[131072];
__device__ __nv_bfloat16 g_xh [1048576],       g_xl [1048576];
__device__ __nv_bfloat16 g_gh [8388608],       g_gl [8388608];
__device__ __nv_bfloat16 g_qh [8388608],       g_ql [8388608];
__device__ __nv_bfloat16 g_kh [8388608],       g_kl [8388608];
__device__ __nv_bfloat16 g_vth[8388608],       g_vtl[8388608];       // [HID][NTOK]
__device__ __nv_bfloat16 g_oh [8388608],       g_ol [8388608];
__device__ __nv_bfloat16 g_ffh[(size_t)NTOK*APAD], g_ffl[(size_t)NTOK*APAD];
__device__ float g_h   [8388608];
__device__ float g_qkvf[(size_t)NTOK*3072];
__device__ float g_bqkv[6*3072];
__device__ float g_b13i[6*5460];
__device__ float g_cos [SEQ*32], g_sin[SEQ*32];

// ---------------------------------------------------------------------------
// PTX helpers
// ---------------------------------------------------------------------------
__device__ __forceinline__ void cp_async16(uint32_t dst, const void* src, int srcbytes) {
    asm volatile("cp.async.cg.shared.global [%0], [%1], 16, %2;\n"
                 :: "r"(dst), "l"(src), "r"(srcbytes));
}
#define CP_COMMIT() asm volatile("cp.async.commit_group;\n" ::)
#define CP_WAIT(n)  asm volatile("cp.async.wait_group %0;\n" :: "n"(n))

#define LDSM4(R0,R1,R2,R3,addr)                                               \
  asm volatile("ldmatrix.sync.aligned.m8n8.x4.shared.b16 {%0,%1,%2,%3}, [%4];"\
               : "=r"(R0),"=r"(R1),"=r"(R2),"=r"(R3) : "r"(addr))

#define MMA16816(d, A0,A1,A2,A3, B0,B1)                                       \
  asm volatile("mma.sync.aligned.m16n8k16.row.col.f32.bf16.bf16.f32 "         \
               "{%0,%1,%2,%3}, {%4,%5,%6,%7}, {%8,%9}, {%0,%1,%2,%3};"        \
               : "+f"(d[0]), "+f"(d[1]), "+f"(d[2]), "+f"(d[3])               \
               : "r"(A0), "r"(A1), "r"(A2), "r"(A3), "r"(B0), "r"(B1))

__device__ __forceinline__ void split_pack(float x, float y, uint32_t& hi, uint32_t& lo) {
    __nv_bfloat16 hx = __float2bfloat16(x);
    __nv_bfloat16 hy = __float2bfloat16(y);
    __nv_bfloat16 lx = __float2bfloat16(x - __bfloat162float(hx));
    __nv_bfloat16 ly = __float2bfloat16(y - __bfloat162float(hy));
    hi = ((uint32_t)__bfloat16_as_ushort(hy) << 16) | __bfloat16_as_ushort(hx);
    lo = ((uint32_t)__bfloat16_as_ushort(ly) << 16) | __bfloat16_as_ushort(lx);
}

// ---------------------------------------------------------------------------
// Fused flash attention (unchanged from R13)
// ---------------------------------------------------------------------------
#define FA_SMEM 110592

__global__ void __launch_bounds__(256, 2)
flash_attn_kernel(const __nv_bfloat16* __restrict__ qh_, const __nv_bfloat16* __restrict__ ql_,
                  const __nv_bfloat16* __restrict__ kh_, const __nv_bfloat16* __restrict__ kl_,
                  const __nv_bfloat16* __restrict__ vh_, const __nv_bfloat16* __restrict__ vl_,
                  __nv_bfloat16* __restrict__ oh_, __nv_bfloat16* __restrict__ ol_)
{
    extern __shared__ __nv_bfloat16 sm[];
    uint32_t sb = (uint32_t)__cvta_generic_to_shared(sm);

    const int tid = threadIdx.x, lane = tid & 31, warp = tid >> 5;
    const int g = lane >> 2, t4 = lane & 3;
    const int rr = lane & 15;
    const int chalf = (lane >> 4) << 3;

    const int bh = blockIdx.y;
    const int b = bh >> 4, h = bh & 15;
    const int tok0 = b * SEQ + blockIdx.x * 128;
    const int h64 = h * HEADDIM;

    #pragma unroll
    for (int i = 0; i < 4; i++) {
        int idx = tid + i * 256;
        int r = idx >> 3, ch = idx & 7;
        long long src = (long long)(tok0 + r) * HID + h64 + ch * 8;
        uint32_t d = sb + (uint32_t)(r * 72 + ch * 8) * 2;
        cp_async16(d,           qh_ + src, 16);
        cp_async16(d + 9216*2,  ql_ + src, 16);
    }

    auto loadKV = [&](int stage, int t) {
        uint32_t st = sb + (uint32_t)(18432 + stage * 18432) * 2;
        #pragma unroll
        for (int i = 0; i < 2; i++) {
            int idx = tid + i * 256;
            int r = idx >> 3, ch = idx & 7;
            long long ksrc = (long long)(b * SEQ + t * 64 + r) * HID + h64 + ch * 8;
            uint32_t kd = st + (uint32_t)(r * 72 + ch * 8) * 2;
            cp_async16(kd,            kh_ + ksrc, 16);
            cp_async16(kd + 4608*2,   kl_ + ksrc, 16);
            long long vsrc = (long long)(h64 + r) * NTOK + b * SEQ + t * 64 + ch * 8;
            uint32_t vd = st + (uint32_t)(9216 + r * 72 + ch * 8) * 2;
            cp_async16(vd,            vh_ + vsrc, 16);
            cp_async16(vd + 4608*2,   vl_ + vsrc, 16);
        }
    };

    loadKV(0, 0);
    CP_COMMIT();

    float oacc[8][4];
    #pragma unroll
    for (int nt = 0; nt < 8; nt++)
        #pragma unroll
        for (int e = 0; e < 4; e++) oacc[nt][e] = 0.f;
    float m0 = -1e30f, m1 = -1e30f, l0 = 0.f, l1 = 0.f;

    for (int t = 0; t < 8; t++) {
        CP_WAIT(0);
        __syncthreads();
        if (t + 1 < 8) { loadKV((t + 1) & 1, t + 1); CP_COMMIT(); }

        const uint32_t KHb = 18432u + (uint32_t)(t & 1) * 18432u;
        const uint32_t VHb = KHb + 9216u;

        float sacc[8][4];
        #pragma unroll
        for (int nt = 0; nt < 8; nt++)
            #pragma unroll
            for (int e = 0; e < 4; e++) sacc[nt][e] = 0.f;

        #pragma unroll
        for (int ks = 0; ks < 4; ks++) {
            const int c0 = ks * 16 + chalf;
            uint32_t ah[4], al[4];
            uint32_t ad = sb + (uint32_t)((warp * 16 + rr) * 72 + c0) * 2;
            LDSM4(ah[0], ah[1], ah[2], ah[3], ad);
            LDSM4(al[0], al[1], al[2], al[3], ad + 9216*2);
            uint32_t bh4[8][2], bl4[8][2];
            #pragma unroll
            for (int p = 0; p < 4; p++) {
                uint32_t bd = sb + (uint32_t)(KHb + (p * 16 + rr) * 72 + c0) * 2;
                uint32_t r0, r1, r2, r3;
                LDSM4(r0, r1, r2, r3, bd);
                bh4[2*p][0] = r0; bh4[2*p+1][0] = r1; bh4[2*p][1] = r2; bh4[2*p+1][1] = r3;
                LDSM4(r0, r1, r2, r3, bd + 4608*2);
                bl4[2*p][0] = r0; bl4[2*p+1][0] = r1; bl4[2*p][1] = r2; bl4[2*p+1][1] = r3;
            }
            #pragma unroll
            for (int nt = 0; nt < 8; nt++)
                MMA16816(sacc[nt], ah[0],ah[1],ah[2],ah[3], bh4[nt][0], bh4[nt][1]);
            #pragma unroll
            for (int nt = 0; nt < 8; nt++)
                MMA16816(sacc[nt], ah[0],ah[1],ah[2],ah[3], bl4[nt][0], bl4[nt][1]);
            #pragma unroll
            for (int nt = 0; nt < 8; nt++)
                MMA16816(sacc[nt], al[0],al[1],al[2],al[3], bh4[nt][0], bh4[nt][1]);
        }

        float mx0 = -1e30f, mx1 = -1e30f;
        #pragma unroll
        for (int nt = 0; nt < 8; nt++) {
            sacc[nt][0] *= 0.125f; sacc[nt][1] *= 0.125f;
            sacc[nt][2] *= 0.125f; sacc[nt][3] *= 0.125f;
            mx0 = fmaxf(mx0, fmaxf(sacc[nt][0], sacc[nt][1]));
            mx1 = fmaxf(mx1, fmaxf(sacc[nt][2], sacc[nt][3]));
        }
        mx0 = fmaxf(mx0, __shfl_xor_sync(0xffffffffu, mx0, 1));
        mx0 = fmaxf(mx0, __shfl_xor_sync(0xffffffffu, mx0, 2));
        mx1 = fmaxf(mx1, __shfl_xor_sync(0xffffffffu, mx1, 1));
        mx1 = fmaxf(mx1, __shfl_xor_sync(0xffffffffu, mx1, 2));
        float mn0 = fmaxf(m0, mx0), mn1 = fmaxf(m1, mx1);
        float sc0 = __expf(m0 - mn0), sc1 = __expf(m1 - mn1);
        float rs0 = 0.f, rs1 = 0.f;
        #pragma unroll
        for (int nt = 0; nt < 8; nt++) {
            sacc[nt][0] = __expf(sacc[nt][0] - mn0); rs0 += sacc[nt][0];
            sacc[nt][1] = __expf(sacc[nt][1] - mn0); rs0 += sacc[nt][1];
            sacc[nt][2] = __expf(sacc[nt][2] - mn1); rs1 += sacc[nt][2];
            sacc[nt][3] = __expf(sacc[nt][3] - mn1); rs1 += sacc[nt][3];
        }
        rs0 += __shfl_xor_sync(0xffffffffu, rs0, 1);
        rs0 += __shfl_xor_sync(0xffffffffu, rs0, 2);
        rs1 += __shfl_xor_sync(0xffffffffu, rs1, 1);
        rs1 += __shfl_xor_sync(0xffffffffu, rs1, 2);
        l0 = l0 * sc0 + rs0;  l1 = l1 * sc1 + rs1;
        m0 = mn0;  m1 = mn1;
        #pragma unroll
        for (int nt = 0; nt < 8; nt++) {
            oacc[nt][0] *= sc0; oacc[nt][1] *= sc0;
            oacc[nt][2] *= sc1; oacc[nt][3] *= sc1;
        }

        #pragma unroll
        for (int j = 0; j < 4; j++) {
            uint32_t aPh[4], aPl[4];
            split_pack(sacc[2*j  ][0], sacc[2*j  ][1], aPh[0], aPl[0]);
            split_pack(sacc[2*j  ][2], sacc[2*j  ][3], aPh[1], aPl[1]);
            split_pack(sacc[2*j+1][0], sacc[2*j+1][1], aPh[2], aPl[2]);
            split_pack(sacc[2*j+1][2], sacc[2*j+1][3], aPh[3], aPl[3]);
            const int c0v = j * 16 + chalf;
            uint32_t bvh[8][2], bvl[8][2];
            #pragma unroll
            for (int p = 0; p < 4; p++) {
                uint32_t bd = sb + (uint32_t)(VHb + (p * 16 + rr) * 72 + c0v) * 2;
                uint32_t r0, r1, r2, r3;
                LDSM4(r0, r1, r2, r3, bd);
                bvh[2*p][0] = r0; bvh[2*p+1][0] = r1; bvh[2*p][1] = r2; bvh[2*p+1][1] = r3;
                LDSM4(r0, r1, r2, r3, bd + 4608*2);
                bvl[2*p][0] = r0; bvl[2*p+1][0] = r1; bvl[2*p][1] = r2; bvl[2*p+1][1] = r3;
            }
            #pragma unroll
            for (int nt = 0; nt < 8; nt++)
                MMA16816(oacc[nt], aPh[0],aPh[1],aPh[2],aPh[3], bvh[nt][0], bvh[nt][1]);
            #pragma unroll
            for (int nt = 0; nt < 8; nt++)
                MMA16816(oacc[nt], aPl[0],aPl[1],aPl[2],aPl[3], bvh[nt][0], bvh[nt][1]);
            #pragma unroll
            for (int nt = 0; nt < 8; nt++)
                MMA16816(oacc[nt], aPh[0],aPh[1],aPh[2],aPh[3], bvl[nt][0], bvl[nt][1]);
        }
    }

    float inv0 = 1.f / l0, inv1 = 1.f / l1;
    const int row0 = tok0 + warp * 16 + g;
    #pragma unroll
    for (int nt = 0; nt < 8; nt++) {
        int c = h64 + nt * 8 + 2 * t4;
        uint32_t hi, lo;
        split_pack(oacc[nt][0] * inv0, oacc[nt][1] * inv0, hi, lo);
        long long off = (long long)row0 * HID + c;
        *(uint32_t*)(oh_ + off) = hi;
        *(uint32_t*)(ol_ + off) = lo;
        split_pack(oacc[nt][2] * inv1, oacc[nt][3] * inv1, hi, lo);
        off = (long long)(row0 + 8) * HID + c;
        *(uint32_t*)(oh_ + off) = hi;
        *(uint32_t*)(ol_ + off) = lo;
    }
}

// ---------------------------------------------------------------------------
// Pipelined bf16 split GEMM — 128 threads/CTA, 64x64 warp tiles (WR=2,WC=2),
// 2 CTAs/SM, double-buffered. Smem-read redundancy (2+2) vs old (4+2).
// ---------------------------------------------------------------------------
template<int NT, int WR, int WC>
__global__ void __launch_bounds__(128, 2)
gemm_mma_kernel(const __nv_bfloat16* __restrict__ Ah, const __nv_bfloat16* __restrict__ Al,
                const __nv_bfloat16* __restrict__ Bh, const __nv_bfloat16* __restrict__ Bl,
                float* __restrict__ C, __nv_bfloat16* __restrict__ Ch, __nv_bfloat16* __restrict__ Cl,
                const float* __restrict__ bias,
                int M, int N, int K, int lda, int ldb, int ldc,
                float alpha, int accum, int outmode)
{
    constexpr int WTM = 128 / WR;
    constexpr int WTN = NT / WC;
    constexpr int MT  = WTM / 16;
    constexpr int NTT = WTN / 8;
    constexpr int NH  = NTT / 4;
    constexpr int APLANE = 128 * SPITCH;
    constexpr int BPLANE = NT * SPITCH;
    constexpr int STAGE_E = 2*APLANE + 2*BPLANE;

    extern __shared__ __nv_bfloat16 smem[];
    uint32_t sbase = (uint32_t)__cvta_generic_to_shared(smem);

    const int tid = threadIdx.x, lane = tid & 31, warp = tid >> 5;
    const int wm = warp / WC, wn = warp % WC;

    const int m0 = blockIdx.y * 128, n0 = blockIdx.x * NT;
    const int T = (K + 31) >> 5;

    auto load_stage = [&](int stg, int k0) {
        uint32_t st = sbase + (uint32_t)stg * (STAGE_E * 2);
        #pragma unroll
        for (int i = 0; i < 4; i++) {               // A: 128 rows x 4 chunks / 128 thr
            int idx = tid + i*128;
            int r = idx >> 2, ch = idx & 3;
            int k = k0 + ch*8;
            int s = (K - k) * 2; s = s < 0 ? 0 : (s > 16 ? 16 : s);
            long long aoff = (long long)(m0 + r) * lda + (s ? k : 0);
            uint32_t d = st + (uint32_t)(r*SPITCH + ch*8)*2;
            cp_async16(d,            Ah + aoff, s);
            cp_async16(d + APLANE*2, Al + aoff, s);
        }
        #pragma unroll
        for (int i = 0; i < NT/32; i++) {           // B: NT rows x 4 chunks / 128 thr
            int idx = tid + i*128;
            int r = idx >> 2, ch = idx & 3;
            int n = n0 + r;
            int k = k0 + ch*8;
            int s = (K - k) * 2; s = s < 0 ? 0 : (s > 16 ? 16 : s);
            if (n >= N) s = 0;
            long long boff = (long long)(n < N ? n : 0) * ldb + (s ? k : 0);
            uint32_t d = st + (uint32_t)(2*APLANE + r*SPITCH + ch*8)*2;
            cp_async16(d,            Bh + boff, s);
            cp_async16(d + BPLANE*2, Bl + boff, s);
        }
    };

    load_stage(0, 0);
    CP_COMMIT();

    float acc[MT][NTT][4];
    #pragma unroll
    for (int i = 0; i < MT; i++)
        #pragma unroll
        for (int j = 0; j < NTT; j++)
            #pragma unroll
            for (int e = 0; e < 4; e++) acc[i][j][e] = 0.f;

    for (int kt = 0; kt < T; kt++) {
        CP_WAIT(0);
        __syncthreads();
        if (kt + 1 < T) { load_stage((kt + 1) & 1, (kt + 1) * 32); CP_COMMIT(); }

        uint32_t st = sbase + (uint32_t)((kt & 1) * (STAGE_E * 2));
        #pragma unroll
        for (int ks = 0; ks < 2; ks++) {
            const int c0 = ks*16 + ((lane >> 4) << 3);
            const int rr = lane & 15;
            uint32_t ah[MT][4], al[MT][4];
            #pragma unroll
            for (int mt = 0; mt < MT; mt++) {
                uint32_t ad = st + (uint32_t)(((wm*WTM + mt*16 + rr)*SPITCH + c0)*2);
                LDSM4(ah[mt][0], ah[mt][1], ah[mt][2], ah[mt][3], ad);
                LDSM4(al[mt][0], al[mt][1], al[mt][2], al[mt][3], ad + APLANE*2);
            }
            #pragma unroll
            for (int half = 0; half < NH; half++) {
                uint32_t bh4[4][2], bl4[4][2];
                #pragma unroll
                for (int p = 0; p < 2; p++) {
                    uint32_t bd = st + (uint32_t)((2*APLANE +
                                  (wn*WTN + half*32 + p*16 + rr)*SPITCH + c0)*2);
                    uint32_t r0, r1, r2, r3;
                    LDSM4(r0, r1, r2, r3, bd);
                    bh4[2*p][0] = r0; bh4[2*p+1][0] = r1; bh4[2*p][1] = r2; bh4[2*p+1][1] = r3;
                    LDSM4(r0, r1, r2, r3, bd + BPLANE*2);
                    bl4[2*p][0] = r0; bl4[2*p+1][0] = r1; bl4[2*p][1] = r2; bl4[2*p+1][1] = r3;
                }
                #pragma unroll
                for (int mt = 0; mt < MT; mt++)
                    #pragma unroll
                    for (int j = 0; j < 4; j++)
                        MMA16816(acc[mt][half*4+j], ah[mt][0],ah[mt][1],ah[mt][2],ah[mt][3], bh4[j][0],bh4[j][1]);
                #pragma unroll
                for (int mt = 0; mt < MT; mt++)
                    #pragma unroll
                    for (int j = 0; j < 4; j++)
                        MMA16816(acc[mt][half*4+j], ah[mt][0],ah[mt][1],ah[mt][2],ah[mt][3], bl4[j][0],bl4[j][1]);
                #pragma unroll
                for (int mt = 0; mt < MT; mt++)
                    #pragma unroll
                    for (int j = 0; j < 4; j++)
                        MMA16816(acc[mt][half*4+j], al[mt][0],al[mt][1],al[mt][2],al[mt][3], bh4[j][0],bh4[j][1]);
            }
        }
    }

    const int g = lane >> 2, t4 = lane & 3;
    #pragma unroll
    for (int mt = 0; mt < MT; mt++)
        #pragma unroll
        for (int nt = 0; nt < NTT; nt++) {
            int r = m0 + wm*WTM + mt*16 + g;
            int c = n0 + wn*WTN + nt*8 + 2*t4;
            if (c < N) {
                float bv0 = 0.f, bv1 = 0.f;
                if (bias) { bv0 = bias[c]; bv1 = bias[c+1]; }
                #pragma unroll
                for (int hh = 0; hh < 2; hh++) {
                    int rr = r + hh*8;
                    float v0 = acc[mt][nt][hh*2+0] + bv0;
                    float v1 = acc[mt][nt][hh*2+1] + bv1;
                    if (outmode == 0) {
                        v0 *= alpha; v1 *= alpha;
                        long long off = (long long)rr * ldc + c;
                        float2 o;
                        if (accum) { float2 p = *(const float2*)(C + off); o.x = p.x + v0; o.y = p.y + v1; }
                        else       { o.x = v0; o.y = v1; }
                        *(float2*)(C + off) = o;
                    } else if (outmode == 1) {
                        v0 *= alpha; v1 *= alpha;
                        long long off = (long long)rr * ldc + c;
                        uint32_t ph, pl;
                        split_pack(v0, v1, ph, pl);
                        *(uint32_t*)(Ch + off) = ph;
                        *(uint32_t*)(Cl + off) = pl;
                    } else {
                        float v = v0 / (1.0f + __expf(-v0)) * v1;
                        long long off = (long long)rr * ldc + (c >> 1);
                        __nv_bfloat16 hi = __float2bfloat16(v);
                        Ch[off] = hi;
                        Cl[off] = __float2bfloat16(v - __bfloat162float(hi));
                    }
                }
            }
        }
}

// ---------------------------------------------------------------------------
// Producers / converters
// ---------------------------------------------------------------------------
// merged init: blocks [0,4096) split x; [4096,4160) rope cache;
// [4160,4232) concat qkv bias; [4232,4296) interleave b1/b3
__global__ void init_misc_kernel(const float* __restrict__ x,
                                 __nv_bfloat16* __restrict__ xh, __nv_bfloat16* __restrict__ xl,
                                 const float* __restrict__ bq, const float* __restrict__ bk,
                                 const float* __restrict__ bv,
                                 const float* __restrict__ b1, const float* __restrict__ b3,
                                 float* __restrict__ bqkv, float* __restrict__ b13i)
{
    int blk = blockIdx.x, tid = threadIdx.x;
    if (blk < 4096) {
        int i = blk * 256 + tid;
        float v = x[i];
        __nv_bfloat16 hi = __float2bfloat16(v);
        xh[i] = hi;
        xl[i] = __float2bfloat16(v - __bfloat162float(hi));
    } else if (blk < 4160) {
        int i = (blk - 4096) * 256 + tid;
        if (i < SEQ * 32) {
            int s = i >> 5, j = i & 31;
            float invf = expf(-(float)j * (1.0f / 32.0f) * logf(10000.0f));
            float a = (float)s * invf;
            g_cos[i] = cosf(a);
            g_sin[i] = sinf(a);
        }
    } else if (blk < 4232) {
        int i = (blk - 4160) * 256 + tid;
        if (i < NLAYER * 3072) {
            int l = i / 3072, r = i - l * 3072;
            float v;
            if (r < HID)            v = bq[l*HID + r];
            else if (r < 2*HID)     v = bk[l*HID + (r - HID)];
            else                    v = bv[l*HID + (r - 2*HID)];
            bqkv[i] = v;
        }
    } else {
        int i = (blk - 4232) * 256 + tid;
        if (i < NLAYER * AHID) {
            int l = i / AHID, j = i - l * AHID;
            b13i[(long long)l*5460 + 2*j]     = b1[(long long)l*AHID + j];
            b13i[(long long)l*5460 + 2*j + 1] = b3[(long long)l*AHID + j];
        }
    }
}

__global__ void transpose_split_kernel(const float* __restrict__ src,
                                       __nv_bfloat16* __restrict__ dh,
                                       __nv_bfloat16* __restrict__ dl,
                                       int R, int C, int srcPitch, int dstPitch,
                                       int rowMul, int rowAdd,
                                       long long srcZ, long long dstZ)
{
    __shared__ float t[32][33];
    long long so = (long long)blockIdx.z * srcZ;
    long long dofs = (long long)blockIdx.z * dstZ;
    int c0 = blockIdx.x*32, r0 = blockIdx.y*32;
    #pragma unroll
    for (int i = threadIdx.y; i < 32; i += 8) {
        int r = r0 + i, c = c0 + threadIdx.x;
        t[i][threadIdx.x] = (r < R && c < C) ? src[so + (long long)r*srcPitch + c] : 0.f;
    }
    __syncthreads();
    #pragma unroll
    for (int i = threadIdx.y; i < 32; i += 8) {
        int c = c0 + i, r = r0 + threadIdx.x;
        if (c < C && r < R) {
            float v = t[threadIdx.x][i];
            __nv_bfloat16 hi = __float2bfloat16(v);
            long long o = dofs + (long long)(c*rowMul + rowAdd)*dstPitch + r;
            dh[o] = hi;
            dl[o] = __float2bfloat16(v - __bfloat162float(hi));
        }
    }
}

// all three qkv weights, all layers, in one launch: z in [0,18)
__global__ void transpose_qkv_kernel(const float* __restrict__ wq, const float* __restrict__ wk,
                                     const float* __restrict__ wv,
                                     __nv_bfloat16* __restrict__ dh, __nv_bfloat16* __restrict__ dl)
{
    __shared__ float t[32][33];
    const long long HH  = (long long)HID*HID;
    const long long QKV = (long long)3072*HID;
    int which = blockIdx.z / NLAYER, l = blockIdx.z % NLAYER;
    const float* src = (which == 0 ? wq : which == 1 ? wk : wv) + (long long)l * HH;
    long long dofs = (long long)l * QKV + (long long)which * HID * HID;
    int c0 = blockIdx.x*32, r0 = blockIdx.y*32;
    #pragma unroll
    for (int i = threadIdx.y; i < 32; i += 8) {
        int r = r0 + i, c = c0 + threadIdx.x;
        t[i][threadIdx.x] = src[(long long)r*HID + c];
    }
    __syncthreads();
    #pragma unroll
    for (int i = threadIdx.y; i < 32; i += 8) {
        int c = c0 + i, r = r0 + threadIdx.x;
        float v = t[threadIdx.x][i];
        __nv_bfloat16 hi = __float2bfloat16(v);
        long long o = dofs + (long long)c*HID + r;
        dh[o] = hi;
        dl[o] = __float2bfloat16(v - __bfloat162float(hi));
    }
}

__global__ void rmsnorm_kernel(const float* __restrict__ x, const float* __restrict__ w,
                               __nv_bfloat16* __restrict__ oh, __nv_bfloat16* __restrict__ ol)
{
    long long row = blockIdx.x;
    const float* xr = x + row * HID;
    float s = 0.f;
    #pragma unroll
    for (int c = threadIdx.x; c < HID; c += 256) { float v = xr[c]; s += v * v; }
    #pragma unroll
    for (int o = 16; o; o >>= 1) s += __shfl_xor_sync(0xffffffffu, s, o);
    __shared__ float red[8];
    int warp = threadIdx.x >> 5, lane = threadIdx.x & 31;
    if (lane == 0) red[warp] = s;
    __syncthreads();
    float tot = red[0]+red[1]+red[2]+red[3]+red[4]+red[5]+red[6]+red[7];
    float inv = rsqrtf(tot * (1.0f / HID) + RMSEPS);
    #pragma unroll
    for (int c = threadIdx.x; c < HID; c += 256) {
        float v = xr[c] * inv * w[c];
        __nv_bfloat16 hi = __float2bfloat16(v);
        oh[row*HID + c] = hi;
        ol[row*HID + c] = __float2bfloat16(v - __bfloat162float(hi));
    }
}

__global__ void rope_apply_kernel(const float* __restrict__ qkv)
{
    int i = blockIdx.x * blockDim.x + threadIdx.x;
    if (i >= NTOK * NHEAD * 32) return;
    int m = i >> 9, rem = i & 511;
    int h = rem >> 5, j = rem & 31;
    int s = m & (SEQ - 1);
    float c  = g_cos[s*32 + j];
    float sn = g_sin[s*32 + j];
    long long src = (long long)m * 3072 + h * HEADDIM + j;
    long long dst = (long long)m * HID  + h * HEADDIM + j;
    {
        float a = qkv[src], b = qkv[src + 32];
        float v0 = a * c - b * sn, v1 = b * c + a * sn;
        __nv_bfloat16 h0 = __float2bfloat16(v0), h1 = __float2bfloat16(v1);
        g_qh[dst]      = h0; g_ql[dst]      = __float2bfloat16(v0 - __bfloat162float(h0));
        g_qh[dst + 32] = h1; g_ql[dst + 32] = __float2bfloat16(v1 - __bfloat162float(h1));
    }
    {
        float a = qkv[src + HID], b = qkv[src + HID + 32];
        float v0 = a * c - b * sn, v1 = b * c + a * sn;
        __nv_bfloat16 h0 = __float2bfloat16(v0), h1 = __float2bfloat16(v1);
        g_kh[dst]      = h0; g_kl[dst]      = __float2bfloat16(v0 - __bfloat162float(h0));
        g_kh[dst + 32] = h1; g_kl[dst + 32] = __float2bfloat16(v1 - __bfloat162float(h1));
    }
}

// ---------------------------------------------------------------------------
// Host plumbing
// ---------------------------------------------------------------------------
static inline size_t stage_bytes(int NT) { return (size_t)(2*128*SPITCH + 2*NT*SPITCH) * 2; }

static void gemm(const __nv_bfloat16* Ahp, const __nv_bfloat16* Alp,
                 const __nv_bfloat16* Bhp, const __nv_bfloat16* Blp,
                 float* C, __nv_bfloat16* Ch, __nv_bfloat16* Cl,
                 const float* bias, int M, int N, int K, int lda, int ldb, int ldc,
                 float alpha, int accum, int outmode)
{
    dim3 grid((N + 127) / 128, M / 128, 1);
    size_t sm = 2 * stage_bytes(128);
    gemm_mma_kernel<128,2,2><<<grid, 128, sm>>>(Ahp, Alp, Bhp, Blp, C, Ch, Cl, bias,
        M, N, K, lda, ldb, ldc, alpha, accum, outmode);
}

#define SYM(p, s) cudaGetSymbolAddress((void**)&p, s)

extern "C" void kernel_launch(void* const* d_in, const int* in_sizes, int n_in,
                              void* d_out, int out_size)
{
    const float* x       = (const float*)d_in[0];
    const float* in_w    = (const float*)d_in[1];
    const float* in_b    = (const float*)d_in[2];
    const float* norm1_w = (const float*)d_in[3];
    const float* norm2_w = (const float*)d_in[4];
    const float* wq      = (const float*)d_in[5];
    const float* bq      = (const float*)d_in[6];
    const float* wk      = (const float*)d_in[7];
    const float* bk      = (const float*)d_in[8];
    const float* wv      = (const float*)d_in[9];
    const float* bv      = (const float*)d_in[10];
    const float* wo      = (const float*)d_in[11];
    const float* bo      = (const float*)d_in[12];
    const float* w1      = (const float*)d_in[13];
    const float* b1      = (const float*)d_in[14];
    const float* w3      = (const float*)d_in[15];
    const float* b3      = (const float*)d_in[16];
    const float* w2      = (const float*)d_in[17];
    const float* b2      = (const float*)d_in[18];
    const float* onorm_w = (const float*)d_in[19];
    const float* out_w   = (const float*)d_in[20];
    const float* out_b   = (const float*)d_in[21];
    float* out = (float*)d_out;

    cudaFuncSetAttribute(gemm_mma_kernel<128,2,2>,
        cudaFuncAttributeMaxDynamicSharedMemorySize, (int)(2 * stage_bytes(128)));
    cudaFuncSetAttribute(flash_attn_kernel,
        cudaFuncAttributeMaxDynamicSharedMemorySize, FA_SMEM);

    __nv_bfloat16 *winh,*winl,*wqkvh,*wqkvl,*woh,*wol,*w13h,*w13l,*w2h,*w2l,*outwh,*outwl;
    __nv_bfloat16 *xh,*xl,*gh,*gl,*qh,*ql,*kh,*kl,*vth,*vtl,*oh,*ol,*ffh,*ffl;
    float *h,*qkvf,*bqkv,*b13i;
    SYM(winh,g_winh); SYM(winl,g_winl);
    SYM(wqkvh,g_wqkvh); SYM(wqkvl,g_wqkvl);
    SYM(woh,g_woh); SYM(wol,g_wol);
    SYM(w13h,g_w13h); SYM(w13l,g_w13l);
    SYM(w2h,g_w2h); SYM(w2l,g_w2l);
    SYM(outwh,g_outwh); SYM(outwl,g_outwl);
    SYM(xh,g_xh); SYM(xl,g_xl); SYM(gh,g_gh); SYM(gl,g_gl);
    SYM(qh,g_qh); SYM(ql,g_ql); SYM(kh,g_kh); SYM(kl,g_kl);
    SYM(vth,g_vth); SYM(vtl,g_vtl); SYM(oh,g_oh); SYM(ol,g_ol);
    SYM(ffh,g_ffh); SYM(ffl,g_ffl);
    SYM(h,g_h); SYM(qkvf,g_qkvf);
    SYM(bqkv,g_bqkv); SYM(b13i,g_b13i);

    const long long HH  = (long long)HID*HID;
    const long long HA  = (long long)HID*AHID;
    const long long QKV = (long long)3072*HID;
    const long long F13 = (long long)5460*HID;

    dim3 tb(32, 8);

    // #1: merged init (split x + rope cache + biases)
    init_misc_kernel<<<4296, 256>>>(x, xh, xl, bq, bk, bv, b1, b3, bqkv, b13i);
    // #2: transpose in_w
    transpose_split_kernel<<<dim3(32, 4, 1), tb>>>(in_w, winh, winl, DIM, HID, HID, DIM, 1, 0, 0, 0);
    // #3: in-proj GEMM  h = x @ in_w + in_b
    gemm(xh, xl, winh, winl, h, nullptr, nullptr, in_b,
         NTOK, HID, DIM, DIM, DIM, HID, 1.0f, 0, 0);
    // #4: rmsnorm layer 0
    rmsnorm_kernel<<<NTOK, 256>>>(h, norm1_w, gh, gl);
    // #5: all qkv weight transposes in one launch
    transpose_qkv_kernel<<<dim3(32, 32, 18), tb>>>(wq, wk, wv, wqkvh, wqkvl);
    // #6: layer-0 QKV GEMM  <-- ncu (-s 5 -c 1) captures this launch
    gemm(gh, gl, wqkvh, wqkvl, qkvf, nullptr, nullptr, bqkv,
         NTOK, 3072, HID, HID, HID, 3072, 1.0f, 0, 0);

    // remaining weight transposes (before first use in layer 0)
    transpose_split_kernel<<<dim3(32, 32, 6), tb>>>(wo, woh, wol, HID, HID, HID, HID, 1, 0, HH, HH);
    transpose_split_kernel<<<dim3(86, 32, 6), tb>>>(w1, w13h, w13l, HID, AHID, AHID, HID, 2, 0, HA, F13);
    transpose_split_kernel<<<dim3(86, 32, 6), tb>>>(w3, w13h, w13l, HID, AHID, AHID, HID, 2, 1, HA, F13);
    transpose_split_kernel<<<dim3(32, 86, 6), tb>>>(w2, w2h, w2l, AHID, HID, HID, APAD, 1, 0, HA, (long long)HID*APAD);
    transpose_split_kernel<<<dim3(4, 32, 1),  tb>>>(out_w, outwh, outwl, HID, DIM, DIM, HID, 1, 0, 0, 0);

    for (int l = 0; l < NLAYER; l++) {
        if (l > 0) {
            rmsnorm_kernel<<<NTOK, 256>>>(h, norm1_w + (long long)l*HID, gh, gl);
            gemm(gh, gl, wqkvh + l*QKV, wqkvl + l*QKV, qkvf, nullptr, nullptr, bqkv + (long long)l*3072,
                 NTOK, 3072, HID, HID, HID, 3072, 1.0f, 0, 0);
        }

        rope_apply_kernel<<<(NTOK*NHEAD*32 + 255)/256, 256>>>(qkvf);
        transpose_split_kernel<<<dim3(32, 256, 1), tb>>>(qkvf + 2048, vth, vtl,
                                                         NTOK, HID, 3072, NTOK, 1, 0, 0, 0);

        flash_attn_kernel<<<dim3(4, 256), 256, FA_SMEM>>>(qh, ql, kh, kl, vth, vtl, oh, ol);

        gemm(oh, ol, woh + l*HH, wol + l*HH, h, nullptr, nullptr, bo + (long long)l*HID,
             NTOK, HID, HID, HID, HID, HID, RSCALE, 1, 0);

        rmsnorm_kernel<<<NTOK, 256>>>(h, norm2_w + (long long)l*HID, gh, gl);

        gemm(gh, gl, w13h + l*F13, w13l + l*F13, nullptr, ffh, ffl, b13i + (long long)l*5460,
             NTOK, 5460, HID, HID, HID, APAD, 1.0f, 0, 2);

        gemm(ffh, ffl, w2h + (long long)l*HID*APAD, w2l + (long long)l*HID*APAD, h,
             nullptr, nullptr, b2 + (long long)l*HID,
             NTOK, HID, AHID, APAD, APAD, HID, RSCALE, 1, 0);
    }

    rmsnorm_kernel<<<NTOK, 256>>>(h, onorm_w, gh, gl);
    gemm(gh, gl, outwh, outwl, out, nullptr, nullptr, out_b,
         NTOK, DIM, HID, HID, HID, DIM, 1.0f, 0, 0);
}

// round 15
// speedup vs baseline: 1.6153x; 1.6153x over previous
#include <cuda_runtime.h>
#include <cuda_bf16.h>
#include <cstdint>

#define BATCH   16
#define SEQ     512
#define DIM     128
#define HID     1024
#define NLAYER  6
#define NHEAD   16
#define HEADDIM 64
#define AHID    2730
#define APAD    2736
#define NTOK    8192
#define RSCALE  0.4082482904638630f
#define RMSEPS  1e-6f

#define SPITCH  40                // GEMM smem pitch (80B, conflict-free)

// ---------------------------------------------------------------------------
// Device scratch (allocation-free)
// ---------------------------------------------------------------------------
__device__ __nv_bfloat16 g_winh[131072],       g_winl[131072];
__device__ __nv_bfloat16 g_wqkvh[6*3145728],   g_wqkvl[6*3145728];   // [3072][1024]
__device__ __nv_bfloat16 g_woh [6*1048576],    g_wol [6*1048576];
__device__ __nv_bfloat16 g_w13h[6*5591040],    g_w13l[6*5591040];    // [5460][1024] interleaved w1/w3
__device__ __nv_bfloat16 g_w2h [6*1024*APAD],  g_w2l [6*1024*APAD];  // [1024][APAD]
__device__ __nv_bfloat16 g_outwh[131072],      g_outwl[131072];
__device__ __nv_bfloat16 g_xh [1048576],       g_xl [1048576];
__device__ __nv_bfloat16 g_gh [8388608],       g_gl [8388608];
__device__ __nv_bfloat16 g_qh [8388608],       g_ql [8388608];
__device__ __nv_bfloat16 g_kh [8388608],       g_kl [8388608];
__device__ __nv_bfloat16 g_vth[8388608],       g_vtl[8388608];       // [HID][NTOK]
__device__ __nv_bfloat16 g_oh [8388608],       g_ol [8388608];
__device__ __nv_bfloat16 g_ffh[(size_t)NTOK*APAD], g_ffl[(size_t)NTOK*APAD];
__device__ float g_h   [8388608];
__device__ float g_qkvf[(size_t)NTOK*3072];
__device__ float g_bqkv[6*3072];
__device__ float g_b13i[6*5460];
__device__ float g_cos [SEQ*32], g_sin[SEQ*32];

// ---------------------------------------------------------------------------
// PTX helpers
// ---------------------------------------------------------------------------
__device__ __forceinline__ void cp_async16(uint32_t dst, const void* src, int srcbytes) {
    asm volatile("cp.async.cg.shared.global [%0], [%1], 16, %2;\n"
                 :: "r"(dst), "l"(src), "r"(srcbytes));
}
#define CP_COMMIT() asm volatile("cp.async.commit_group;\n" ::)
#define CP_WAIT(n)  asm volatile("cp.async.wait_group %0;\n" :: "n"(n))

#define LDSM4(R0,R1,R2,R3,addr)                                               \
  asm volatile("ldmatrix.sync.aligned.m8n8.x4.shared.b16 {%0,%1,%2,%3}, [%4];"\
               : "=r"(R0),"=r"(R1),"=r"(R2),"=r"(R3) : "r"(addr))

#define MMA16816(d, A0,A1,A2,A3, B0,B1)                                       \
  asm volatile("mma.sync.aligned.m16n8k16.row.col.f32.bf16.bf16.f32 "         \
               "{%0,%1,%2,%3}, {%4,%5,%6,%7}, {%8,%9}, {%0,%1,%2,%3};"        \
               : "+f"(d[0]), "+f"(d[1]), "+f"(d[2]), "+f"(d[3])               \
               : "r"(A0), "r"(A1), "r"(A2), "r"(A3), "r"(B0), "r"(B1))

__device__ __forceinline__ void split_pack(float x, float y, uint32_t& hi, uint32_t& lo) {
    __nv_bfloat16 hx = __float2bfloat16(x);
    __nv_bfloat16 hy = __float2bfloat16(y);
    __nv_bfloat16 lx = __float2bfloat16(x - __bfloat162float(hx));
    __nv_bfloat16 ly = __float2bfloat16(y - __bfloat162float(hy));
    hi = ((uint32_t)__bfloat16_as_ushort(hy) << 16) | __bfloat16_as_ushort(hx);
    lo = ((uint32_t)__bfloat16_as_ushort(ly) << 16) | __bfloat16_as_ushort(lx);
}

// ---------------------------------------------------------------------------
// Fused flash attention (unchanged from R13)
// ---------------------------------------------------------------------------
#define FA_SMEM 110592

__global__ void __launch_bounds__(256, 2)
flash_attn_kernel(const __nv_bfloat16* __restrict__ qh_, const __nv_bfloat16* __restrict__ ql_,
                  const __nv_bfloat16* __restrict__ kh_, const __nv_bfloat16* __restrict__ kl_,
                  const __nv_bfloat16* __restrict__ vh_, const __nv_bfloat16* __restrict__ vl_,
                  __nv_bfloat16* __restrict__ oh_, __nv_bfloat16* __restrict__ ol_)
{
    extern __shared__ __nv_bfloat16 sm[];
    uint32_t sb = (uint32_t)__cvta_generic_to_shared(sm);

    const int tid = threadIdx.x, lane = tid & 31, warp = tid >> 5;
    const int g = lane >> 2, t4 = lane & 3;
    const int rr = lane & 15;
    const int chalf = (lane >> 4) << 3;

    const int bh = blockIdx.y;
    const int b = bh >> 4, h = bh & 15;
    const int tok0 = b * SEQ + blockIdx.x * 128;
    const int h64 = h * HEADDIM;

    #pragma unroll
    for (int i = 0; i < 4; i++) {
        int idx = tid + i * 256;
        int r = idx >> 3, ch = idx & 7;
        long long src = (long long)(tok0 + r) * HID + h64 + ch * 8;
        uint32_t d = sb + (uint32_t)(r * 72 + ch * 8) * 2;
        cp_async16(d,           qh_ + src, 16);
        cp_async16(d + 9216*2,  ql_ + src, 16);
    }

    auto loadKV = [&](int stage, int t) {
        uint32_t st = sb + (uint32_t)(18432 + stage * 18432) * 2;
        #pragma unroll
        for (int i = 0; i < 2; i++) {
            int idx = tid + i * 256;
            int r = idx >> 3, ch = idx & 7;
            long long ksrc = (long long)(b * SEQ + t * 64 + r) * HID + h64 + ch * 8;
            uint32_t kd = st + (uint32_t)(r * 72 + ch * 8) * 2;
            cp_async16(kd,            kh_ + ksrc, 16);
            cp_async16(kd + 4608*2,   kl_ + ksrc, 16);
            long long vsrc = (long long)(h64 + r) * NTOK + b * SEQ + t * 64 + ch * 8;
            uint32_t vd = st + (uint32_t)(9216 + r * 72 + ch * 8) * 2;
            cp_async16(vd,            vh_ + vsrc, 16);
            cp_async16(vd + 4608*2,   vl_ + vsrc, 16);
        }
    };

    loadKV(0, 0);
    CP_COMMIT();

    float oacc[8][4];
    #pragma unroll
    for (int nt = 0; nt < 8; nt++)
        #pragma unroll
        for (int e = 0; e < 4; e++) oacc[nt][e] = 0.f;
    float m0 = -1e30f, m1 = -1e30f, l0 = 0.f, l1 = 0.f;

    for (int t = 0; t < 8; t++) {
        CP_WAIT(0);
        __syncthreads();
        if (t + 1 < 8) { loadKV((t + 1) & 1, t + 1); CP_COMMIT(); }

        const uint32_t KHb = 18432u + (uint32_t)(t & 1) * 18432u;
        const uint32_t VHb = KHb + 9216u;

        float sacc[8][4];
        #pragma unroll
        for (int nt = 0; nt < 8; nt++)
            #pragma unroll
            for (int e = 0; e < 4; e++) sacc[nt][e] = 0.f;

        #pragma unroll
        for (int ks = 0; ks < 4; ks++) {
            const int c0 = ks * 16 + chalf;
            uint32_t ah[4], al[4];
            uint32_t ad = sb + (uint32_t)((warp * 16 + rr) * 72 + c0) * 2;
            LDSM4(ah[0], ah[1], ah[2], ah[3], ad);
            LDSM4(al[0], al[1], al[2], al[3], ad + 9216*2);
            uint32_t bh4[8][2], bl4[8][2];
            #pragma unroll
            for (int p = 0; p < 4; p++) {
                uint32_t bd = sb + (uint32_t)(KHb + (p * 16 + rr) * 72 + c0) * 2;
                uint32_t r0, r1, r2, r3;
                LDSM4(r0, r1, r2, r3, bd);
                bh4[2*p][0] = r0; bh4[2*p+1][0] = r1; bh4[2*p][1] = r2; bh4[2*p+1][1] = r3;
                LDSM4(r0, r1, r2, r3, bd + 4608*2);
                bl4[2*p][0] = r0; bl4[2*p+1][0] = r1; bl4[2*p][1] = r2; bl4[2*p+1][1] = r3;
            }
            #pragma unroll
            for (int nt = 0; nt < 8; nt++)
                MMA16816(sacc[nt], ah[0],ah[1],ah[2],ah[3], bh4[nt][0], bh4[nt][1]);
            #pragma unroll
            for (int nt = 0; nt < 8; nt++)
                MMA16816(sacc[nt], ah[0],ah[1],ah[2],ah[3], bl4[nt][0], bl4[nt][1]);
            #pragma unroll
            for (int nt = 0; nt < 8; nt++)
                MMA16816(sacc[nt], al[0],al[1],al[2],al[3], bh4[nt][0], bh4[nt][1]);
        }

        float mx0 = -1e30f, mx1 = -1e30f;
        #pragma unroll
        for (int nt = 0; nt < 8; nt++) {
            sacc[nt][0] *= 0.125f; sacc[nt][1] *= 0.125f;
            sacc[nt][2] *= 0.125f; sacc[nt][3] *= 0.125f;
            mx0 = fmaxf(mx0, fmaxf(sacc[nt][0], sacc[nt][1]));
            mx1 = fmaxf(mx1, fmaxf(sacc[nt][2], sacc[nt][3]));
        }
        mx0 = fmaxf(mx0, __shfl_xor_sync(0xffffffffu, mx0, 1));
        mx0 = fmaxf(mx0, __shfl_xor_sync(0xffffffffu, mx0, 2));
        mx1 = fmaxf(mx1, __shfl_xor_sync(0xffffffffu, mx1, 1));
        mx1 = fmaxf(mx1, __shfl_xor_sync(0xffffffffu, mx1, 2));
        float mn0 = fmaxf(m0, mx0), mn1 = fmaxf(m1, mx1);
        float sc0 = __expf(m0 - mn0), sc1 = __expf(m1 - mn1);
        float rs0 = 0.f, rs1 = 0.f;
        #pragma unroll
        for (int nt = 0; nt < 8; nt++) {
            sacc[nt][0] = __expf(sacc[nt][0] - mn0); rs0 += sacc[nt][0];
            sacc[nt][1] = __expf(sacc[nt][1] - mn0); rs0 += sacc[nt][1];
            sacc[nt][2] = __expf(sacc[nt][2] - mn1); rs1 += sacc[nt][2];
            sacc[nt][3] = __expf(sacc[nt][3] - mn1); rs1 += sacc[nt][3];
        }
        rs0 += __shfl_xor_sync(0xffffffffu, rs0, 1);
        rs0 += __shfl_xor_sync(0xffffffffu, rs0, 2);
        rs1 += __shfl_xor_sync(0xffffffffu, rs1, 1);
        rs1 += __shfl_xor_sync(0xffffffffu, rs1, 2);
        l0 = l0 * sc0 + rs0;  l1 = l1 * sc1 + rs1;
        m0 = mn0;  m1 = mn1;
        #pragma unroll
        for (int nt = 0; nt < 8; nt++) {
            oacc[nt][0] *= sc0; oacc[nt][1] *= sc0;
            oacc[nt][2] *= sc1; oacc[nt][3] *= sc1;
        }

        #pragma unroll
        for (int j = 0; j < 4; j++) {
            uint32_t aPh[4], aPl[4];
            split_pack(sacc[2*j  ][0], sacc[2*j  ][1], aPh[0], aPl[0]);
            split_pack(sacc[2*j  ][2], sacc[2*j  ][3], aPh[1], aPl[1]);
            split_pack(sacc[2*j+1][0], sacc[2*j+1][1], aPh[2], aPl[2]);
            split_pack(sacc[2*j+1][2], sacc[2*j+1][3], aPh[3], aPl[3]);
            const int c0v = j * 16 + chalf;
            uint32_t bvh[8][2], bvl[8][2];
            #pragma unroll
            for (int p = 0; p < 4; p++) {
                uint32_t bd = sb + (uint32_t)(VHb + (p * 16 + rr) * 72 + c0v) * 2;
                uint32_t r0, r1, r2, r3;
                LDSM4(r0, r1, r2, r3, bd);
                bvh[2*p][0] = r0; bvh[2*p+1][0] = r1; bvh[2*p][1] = r2; bvh[2*p+1][1] = r3;
                LDSM4(r0, r1, r2, r3, bd + 4608*2);
                bvl[2*p][0] = r0; bvl[2*p+1][0] = r1; bvl[2*p][1] = r2; bvl[2*p+1][1] = r3;
            }
            #pragma unroll
            for (int nt = 0; nt < 8; nt++)
                MMA16816(oacc[nt], aPh[0],aPh[1],aPh[2],aPh[3], bvh[nt][0], bvh[nt][1]);
            #pragma unroll
            for (int nt = 0; nt < 8; nt++)
                MMA16816(oacc[nt], aPl[0],aPl[1],aPl[2],aPl[3], bvh[nt][0], bvh[nt][1]);
            #pragma unroll
            for (int nt = 0; nt < 8; nt++)
                MMA16816(oacc[nt], aPh[0],aPh[1],aPh[2],aPh[3], bvl[nt][0], bvl[nt][1]);
        }
    }

    float inv0 = 1.f / l0, inv1 = 1.f / l1;
    const int row0 = tok0 + warp * 16 + g;
    #pragma unroll
    for (int nt = 0; nt < 8; nt++) {
        int c = h64 + nt * 8 + 2 * t4;
        uint32_t hi, lo;
        split_pack(oacc[nt][0] * inv0, oacc[nt][1] * inv0, hi, lo);
        long long off = (long long)row0 * HID + c;
        *(uint32_t*)(oh_ + off) = hi;
        *(uint32_t*)(ol_ + off) = lo;
        split_pack(oacc[nt][2] * inv1, oacc[nt][3] * inv1, hi, lo);
        off = (long long)(row0 + 8) * HID + c;
        *(uint32_t*)(oh_ + off) = hi;
        *(uint32_t*)(ol_ + off) = lo;
    }
}

// ---------------------------------------------------------------------------
// Pipelined bf16 split GEMM — R13-proven config: 256 threads, WR=4 x WC=2
// warp grid (32x64 warp tiles), 2 CTAs/SM, double-buffered BK=32.
// ---------------------------------------------------------------------------
template<int NT, int WR, int WC>
__global__ void __launch_bounds__(256, 2)
gemm_mma_kernel(const __nv_bfloat16* __restrict__ Ah, const __nv_bfloat16* __restrict__ Al,
                const __nv_bfloat16* __restrict__ Bh, const __nv_bfloat16* __restrict__ Bl,
                float* __restrict__ C, __nv_bfloat16* __restrict__ Ch, __nv_bfloat16* __restrict__ Cl,
                const float* __restrict__ bias,
                int M, int N, int K, int lda, int ldb, int ldc,
                float alpha, int accum, int outmode)
{
    constexpr int WTM = 128 / WR;
    constexpr int WTN = NT / WC;
    constexpr int MT  = WTM / 16;
    constexpr int NTT = WTN / 8;
    constexpr int NH  = NTT / 4;
    constexpr int APLANE = 128 * SPITCH;
    constexpr int BPLANE = NT * SPITCH;
    constexpr int STAGE_E = 2*APLANE + 2*BPLANE;

    extern __shared__ __nv_bfloat16 smem[];
    uint32_t sbase = (uint32_t)__cvta_generic_to_shared(smem);

    const int tid = threadIdx.x, lane = tid & 31, warp = tid >> 5;
    const int wm = warp / WC, wn = warp % WC;

    const int m0 = blockIdx.y * 128, n0 = blockIdx.x * NT;
    const int T = (K + 31) >> 5;

    auto load_stage = [&](int stg, int k0) {
        uint32_t st = sbase + (uint32_t)stg * (STAGE_E * 2);
        #pragma unroll
        for (int i = 0; i < 2; i++) {
            int idx = tid + i*256;
            int r = idx >> 2, ch = idx & 3;
            int k = k0 + ch*8;
            int s = (K - k) * 2; s = s < 0 ? 0 : (s > 16 ? 16 : s);
            long long aoff = (long long)(m0 + r) * lda + (s ? k : 0);
            uint32_t d = st + (uint32_t)(r*SPITCH + ch*8)*2;
            cp_async16(d,            Ah + aoff, s);
            cp_async16(d + APLANE*2, Al + aoff, s);
        }
        #pragma unroll
        for (int i = 0; i < NT/64; i++) {
            int idx = tid + i*256;
            int r = idx >> 2, ch = idx & 3;
            int n = n0 + r;
            int k = k0 + ch*8;
            int s = (K - k) * 2; s = s < 0 ? 0 : (s > 16 ? 16 : s);
            if (n >= N) s = 0;
            long long boff = (long long)(n < N ? n : 0) * ldb + (s ? k : 0);
            uint32_t d = st + (uint32_t)(2*APLANE + r*SPITCH + ch*8)*2;
            cp_async16(d,            Bh + boff, s);
            cp_async16(d + BPLANE*2, Bl + boff, s);
        }
    };

    load_stage(0, 0);
    CP_COMMIT();

    float acc[MT][NTT][4];
    #pragma unroll
    for (int i = 0; i < MT; i++)
        #pragma unroll
        for (int j = 0; j < NTT; j++)
            #pragma unroll
            for (int e = 0; e < 4; e++) acc[i][j][e] = 0.f;

    for (int kt = 0; kt < T; kt++) {
        CP_WAIT(0);
        __syncthreads();
        if (kt + 1 < T) { load_stage((kt + 1) & 1, (kt + 1) * 32); CP_COMMIT(); }

        uint32_t st = sbase + (uint32_t)((kt & 1) * (STAGE_E * 2));
        #pragma unroll
        for (int ks = 0; ks < 2; ks++) {
            const int c0 = ks*16 + ((lane >> 4) << 3);
            const int rr = lane & 15;
            uint32_t ah[MT][4], al[MT][4];
            #pragma unroll
            for (int mt = 0; mt < MT; mt++) {
                uint32_t ad = st + (uint32_t)(((wm*WTM + mt*16 + rr)*SPITCH + c0)*2);
                LDSM4(ah[mt][0], ah[mt][1], ah[mt][2], ah[mt][3], ad);
                LDSM4(al[mt][0], al[mt][1], al[mt][2], al[mt][3], ad + APLANE*2);
            }
            #pragma unroll
            for (int half = 0; half < NH; half++) {
                uint32_t bh4[4][2], bl4[4][2];
                #pragma unroll
                for (int p = 0; p < 2; p++) {
                    uint32_t bd = st + (uint32_t)((2*APLANE +
                                  (wn*WTN + half*32 + p*16 + rr)*SPITCH + c0)*2);
                    uint32_t r0, r1, r2, r3;
                    LDSM4(r0, r1, r2, r3, bd);
                    bh4[2*p][0] = r0; bh4[2*p+1][0] = r1; bh4[2*p][1] = r2; bh4[2*p+1][1] = r3;
                    LDSM4(r0, r1, r2, r3, bd + BPLANE*2);
                    bl4[2*p][0] = r0; bl4[2*p+1][0] = r1; bl4[2*p][1] = r2; bl4[2*p+1][1] = r3;
                }
                #pragma unroll
                for (int mt = 0; mt < MT; mt++)
                    #pragma unroll
                    for (int j = 0; j < 4; j++)
                        MMA16816(acc[mt][half*4+j], ah[mt][0],ah[mt][1],ah[mt][2],ah[mt][3], bh4[j][0],bh4[j][1]);
                #pragma unroll
                for (int mt = 0; mt < MT; mt++)
                    #pragma unroll
                    for (int j = 0; j < 4; j++)
                        MMA16816(acc[mt][half*4+j], ah[mt][0],ah[mt][1],ah[mt][2],ah[mt][3], bl4[j][0],bl4[j][1]);
                #pragma unroll
                for (int mt = 0; mt < MT; mt++)
                    #pragma unroll
                    for (int j = 0; j < 4; j++)
                        MMA16816(acc[mt][half*4+j], al[mt][0],al[mt][1],al[mt][2],al[mt][3], bh4[j][0],bh4[j][1]);
            }
        }
    }

    const int g = lane >> 2, t4 = lane & 3;
    #pragma unroll
    for (int mt = 0; mt < MT; mt++)
        #pragma unroll
        for (int nt = 0; nt < NTT; nt++) {
            int r = m0 + wm*WTM + mt*16 + g;
            int c = n0 + wn*WTN + nt*8 + 2*t4;
            if (c < N) {
                float bv0 = 0.f, bv1 = 0.f;
                if (bias) { bv0 = bias[c]; bv1 = bias[c+1]; }
                #pragma unroll
                for (int hh = 0; hh < 2; hh++) {
                    int rr = r + hh*8;
                    float v0 = acc[mt][nt][hh*2+0] + bv0;
                    float v1 = acc[mt][nt][hh*2+1] + bv1;
                    if (outmode == 0) {
                        v0 *= alpha; v1 *= alpha;
                        long long off = (long long)rr * ldc + c;
                        float2 o;
                        if (accum) { float2 p = *(const float2*)(C + off); o.x = p.x + v0; o.y = p.y + v1; }
                        else       { o.x = v0; o.y = v1; }
                        *(float2*)(C + off) = o;
                    } else if (outmode == 1) {
                        v0 *= alpha; v1 *= alpha;
                        long long off = (long long)rr * ldc + c;
                        uint32_t ph, pl;
                        split_pack(v0, v1, ph, pl);
                        *(uint32_t*)(Ch + off) = ph;
                        *(uint32_t*)(Cl + off) = pl;
                    } else {
                        float v = v0 / (1.0f + __expf(-v0)) * v1;
                        long long off = (long long)rr * ldc + (c >> 1);
                        __nv_bfloat16 hi = __float2bfloat16(v);
                        Ch[off] = hi;
                        Cl[off] = __float2bfloat16(v - __bfloat162float(hi));
                    }
                }
            }
        }
}

// ---------------------------------------------------------------------------
// Producers / converters
// ---------------------------------------------------------------------------
__global__ void init_misc_kernel(const float* __restrict__ x,
                                 __nv_bfloat16* __restrict__ xh, __nv_bfloat16* __restrict__ xl,
                                 const float* __restrict__ bq, const float* __restrict__ bk,
                                 const float* __restrict__ bv,
                                 const float* __restrict__ b1, const float* __restrict__ b3,
                                 float* __restrict__ bqkv, float* __restrict__ b13i)
{
    int blk = blockIdx.x, tid = threadIdx.x;
    if (blk < 4096) {
        int i = blk * 256 + tid;
        float v = x[i];
        __nv_bfloat16 hi = __float2bfloat16(v);
        xh[i] = hi;
        xl[i] = __float2bfloat16(v - __bfloat162float(hi));
    } else if (blk < 4160) {
        int i = (blk - 4096) * 256 + tid;
        if (i < SEQ * 32) {
            int s = i >> 5, j = i & 31;
            float invf = expf(-(float)j * (1.0f / 32.0f) * logf(10000.0f));
            float a = (float)s * invf;
            g_cos[i] = cosf(a);
            g_sin[i] = sinf(a);
        }
    } else if (blk < 4232) {
        int i = (blk - 4160) * 256 + tid;
        if (i < NLAYER * 3072) {
            int l = i / 3072, r = i - l * 3072;
            float v;
            if (r < HID)            v = bq[l*HID + r];
            else if (r < 2*HID)     v = bk[l*HID + (r - HID)];
            else                    v = bv[l*HID + (r - 2*HID)];
            bqkv[i] = v;
        }
    } else {
        int i = (blk - 4232) * 256 + tid;
        if (i < NLAYER * AHID) {
            int l = i / AHID, j = i - l * AHID;
            b13i[(long long)l*5460 + 2*j]     = b1[(long long)l*AHID + j];
            b13i[(long long)l*5460 + 2*j + 1] = b3[(long long)l*AHID + j];
        }
    }
}

__global__ void transpose_split_kernel(const float* __restrict__ src,
                                       __nv_bfloat16* __restrict__ dh,
                                       __nv_bfloat16* __restrict__ dl,
                                       int R, int C, int srcPitch, int dstPitch,
                                       int rowMul, int rowAdd,
                                       long long srcZ, long long dstZ)
{
    __shared__ float t[32][33];
    long long so = (long long)blockIdx.z * srcZ;
    long long dofs = (long long)blockIdx.z * dstZ;
    int c0 = blockIdx.x*32, r0 = blockIdx.y*32;
    #pragma unroll
    for (int i = threadIdx.y; i < 32; i += 8) {
        int r = r0 + i, c = c0 + threadIdx.x;
        t[i][threadIdx.x] = (r < R && c < C) ? src[so + (long long)r*srcPitch + c] : 0.f;
    }
    __syncthreads();
    #pragma unroll
    for (int i = threadIdx.y; i < 32; i += 8) {
        int c = c0 + i, r = r0 + threadIdx.x;
        if (c < C && r < R) {
            float v = t[threadIdx.x][i];
            __nv_bfloat16 hi = __float2bfloat16(v);
            long long o = dofs + (long long)(c*rowMul + rowAdd)*dstPitch + r;
            dh[o] = hi;
            dl[o] = __float2bfloat16(v - __bfloat162float(hi));
        }
    }
}

__global__ void transpose_qkv_kernel(const float* __restrict__ wq, const float* __restrict__ wk,
                                     const float* __restrict__ wv,
                                     __nv_bfloat16* __restrict__ dh, __nv_bfloat16* __restrict__ dl)
{
    __shared__ float t[32][33];
    const long long HH  = (long long)HID*HID;
    const long long QKV = (long long)3072*HID;
    int which = blockIdx.z / NLAYER, l = blockIdx.z % NLAYER;
    const float* src = (which == 0 ? wq : which == 1 ? wk : wv) + (long long)l * HH;
    long long dofs = (long long)l * QKV + (long long)which * HID * HID;
    int c0 = blockIdx.x*32, r0 = blockIdx.y*32;
    #pragma unroll
    for (int i = threadIdx.y; i < 32; i += 8) {
        int r = r0 + i, c = c0 + threadIdx.x;
        t[i][threadIdx.x] = src[(long long)r*HID + c];
    }
    __syncthreads();
    #pragma unroll
    for (int i = threadIdx.y; i < 32; i += 8) {
        int c = c0 + i, r = r0 + threadIdx.x;
        float v = t[threadIdx.x][i];
        __nv_bfloat16 hi = __float2bfloat16(v);
        long long o = dofs + (long long)c*HID + r;
        dh[o] = hi;
        dl[o] = __float2bfloat16(v - __bfloat162float(hi));
    }
}

// vectorized: 256 threads x float4 = 1024 elems/row exactly
__global__ void rmsnorm_kernel(const float* __restrict__ x, const float* __restrict__ w,
                               __nv_bfloat16* __restrict__ oh, __nv_bfloat16* __restrict__ ol)
{
    long long row = blockIdx.x;
    int c = threadIdx.x * 4;
    float4 v4 = *(const float4*)(x + row * HID + c);
    float s = v4.x*v4.x + v4.y*v4.y + v4.z*v4.z + v4.w*v4.w;
    #pragma unroll
    for (int o = 16; o; o >>= 1) s += __shfl_xor_sync(0xffffffffu, s, o);
    __shared__ float red[8];
    int warp = threadIdx.x >> 5, lane = threadIdx.x & 31;
    if (lane == 0) red[warp] = s;
    __syncthreads();
    float tot = red[0]+red[1]+red[2]+red[3]+red[4]+red[5]+red[6]+red[7];
    float inv = rsqrtf(tot * (1.0f / HID) + RMSEPS);
    float4 w4 = *(const float4*)(w + c);
    float a0 = v4.x * inv * w4.x, a1 = v4.y * inv * w4.y;
    float a2 = v4.z * inv * w4.z, a3 = v4.w * inv * w4.w;
    uint32_t h01, l01, h23, l23;
    split_pack(a0, a1, h01, l01);
    split_pack(a2, a3, h23, l23);
    uint2 hv = make_uint2(h01, h23), lv = make_uint2(l01, l23);
    *(uint2*)(oh + row * HID + c) = hv;
    *(uint2*)(ol + row * HID + c) = lv;
}

__global__ void rope_apply_kernel(const float* __restrict__ qkv)
{
    int i = blockIdx.x * blockDim.x + threadIdx.x;
    if (i >= NTOK * NHEAD * 32) return;
    int m = i >> 9, rem = i & 511;
    int h = rem >> 5, j = rem & 31;
    int s = m & (SEQ - 1);
    float c  = g_cos[s*32 + j];
    float sn = g_sin[s*32 + j];
    long long src = (long long)m * 3072 + h * HEADDIM + j;
    long long dst = (long long)m * HID  + h * HEADDIM + j;
    {
        float a = qkv[src], b = qkv[src + 32];
        float v0 = a * c - b * sn, v1 = b * c + a * sn;
        __nv_bfloat16 h0 = __float2bfloat16(v0), h1 = __float2bfloat16(v1);
        g_qh[dst]      = h0; g_ql[dst]      = __float2bfloat16(v0 - __bfloat162float(h0));
        g_qh[dst + 32] = h1; g_ql[dst + 32] = __float2bfloat16(v1 - __bfloat162float(h1));
    }
    {
        float a = qkv[src + HID], b = qkv[src + HID + 32];
        float v0 = a * c - b * sn, v1 = b * c + a * sn;
        __nv_bfloat16 h0 = __float2bfloat16(v0), h1 = __float2bfloat16(v1);
        g_kh[dst]      = h0; g_kl[dst]      = __float2bfloat16(v0 - __bfloat162float(h0));
        g_kh[dst + 32] = h1; g_kl[dst + 32] = __float2bfloat16(v1 - __bfloat162float(h1));
    }
}

// ---------------------------------------------------------------------------
// Host plumbing
// ---------------------------------------------------------------------------
static inline size_t stage_bytes(int NT) { return (size_t)(2*128*SPITCH + 2*NT*SPITCH) * 2; }

static void gemm(const __nv_bfloat16* Ahp, const __nv_bfloat16* Alp,
                 const __nv_bfloat16* Bhp, const __nv_bfloat16* Blp,
                 float* C, __nv_bfloat16* Ch, __nv_bfloat16* Cl,
                 const float* bias, int M, int N, int K, int lda, int ldb, int ldc,
                 float alpha, int accum, int outmode)
{
    dim3 grid((N + 127) / 128, M / 128, 1);
    size_t sm = 2 * stage_bytes(128);
    gemm_mma_kernel<128,4,2><<<grid, 256, sm>>>(Ahp, Alp, Bhp, Blp, C, Ch, Cl, bias,
        M, N, K, lda, ldb, ldc, alpha, accum, outmode);
}

#define SYM(p, s) cudaGetSymbolAddress((void**)&p, s)

extern "C" void kernel_launch(void* const* d_in, const int* in_sizes, int n_in,
                              void* d_out, int out_size)
{
    const float* x       = (const float*)d_in[0];
    const float* in_w    = (const float*)d_in[1];
    const float* in_b    = (const float*)d_in[2];
    const float* norm1_w = (const float*)d_in[3];
    const float* norm2_w = (const float*)d_in[4];
    const float* wq      = (const float*)d_in[5];
    const float* bq      = (const float*)d_in[6];
    const float* wk      = (const float*)d_in[7];
    const float* bk      = (const float*)d_in[8];
    const float* wv      = (const float*)d_in[9];
    const float* bv      = (const float*)d_in[10];
    const float* wo      = (const float*)d_in[11];
    const float* bo      = (const float*)d_in[12];
    const float* w1      = (const float*)d_in[13];
    const float* b1      = (const float*)d_in[14];
    const float* w3      = (const float*)d_in[15];
    const float* b3      = (const float*)d_in[16];
    const float* w2      = (const float*)d_in[17];
    const float* b2      = (const float*)d_in[18];
    const float* onorm_w = (const float*)d_in[19];
    const float* out_w   = (const float*)d_in[20];
    const float* out_b   = (const float*)d_in[21];
    float* out = (float*)d_out;

    cudaFuncSetAttribute(gemm_mma_kernel<128,4,2>,
        cudaFuncAttributeMaxDynamicSharedMemorySize, (int)(2 * stage_bytes(128)));
    cudaFuncSetAttribute(flash_attn_kernel,
        cudaFuncAttributeMaxDynamicSharedMemorySize, FA_SMEM);

    __nv_bfloat16 *winh,*winl,*wqkvh,*wqkvl,*woh,*wol,*w13h,*w13l,*w2h,*w2l,*outwh,*outwl;
    __nv_bfloat16 *xh,*xl,*gh,*gl,*qh,*ql,*kh,*kl,*vth,*vtl,*oh,*ol,*ffh,*ffl;
    float *h,*qkvf,*bqkv,*b13i;
    SYM(winh,g_winh); SYM(winl,g_winl);
    SYM(wqkvh,g_wqkvh); SYM(wqkvl,g_wqkvl);
    SYM(woh,g_woh); SYM(wol,g_wol);
    SYM(w13h,g_w13h); SYM(w13l,g_w13l);
    SYM(w2h,g_w2h); SYM(w2l,g_w2l);
    SYM(outwh,g_outwh); SYM(outwl,g_outwl);
    SYM(xh,g_xh); SYM(xl,g_xl); SYM(gh,g_gh); SYM(gl,g_gl);
    SYM(qh,g_qh); SYM(ql,g_ql); SYM(kh,g_kh); SYM(kl,g_kl);
    SYM(vth,g_vth); SYM(vtl,g_vtl); SYM(oh,g_oh); SYM(ol,g_ol);
    SYM(ffh,g_ffh); SYM(ffl,g_ffl);
    SYM(h,g_h); SYM(qkvf,g_qkvf);
    SYM(bqkv,g_bqkv); SYM(b13i,g_b13i);

    const long long HH  = (long long)HID*HID;
    const long long HA  = (long long)HID*AHID;
    const long long QKV = (long long)3072*HID;
    const long long F13 = (long long)5460*HID;

    dim3 tb(32, 8);

    // #1: merged init (split x + rope cache + biases)
    init_misc_kernel<<<4296, 256>>>(x, xh, xl, bq, bk, bv, b1, b3, bqkv, b13i);
    // #2: transpose in_w
    transpose_split_kernel<<<dim3(32, 4, 1), tb>>>(in_w, winh, winl, DIM, HID, HID, DIM, 1, 0, 0, 0);
    // #3: in-proj GEMM  h = x @ in_w + in_b
    gemm(xh, xl, winh, winl, h, nullptr, nullptr, in_b,
         NTOK, HID, DIM, DIM, DIM, HID, 1.0f, 0, 0);
    // #4: rmsnorm layer 0
    rmsnorm_kernel<<<NTOK, 256>>>(h, norm1_w, gh, gl);
    // #5: all qkv weight transposes in one launch
    transpose_qkv_kernel<<<dim3(32, 32, 18), tb>>>(wq, wk, wv, wqkvh, wqkvl);
    // #6: layer-0 QKV GEMM  <-- ncu (-s 5 -c 1) captures this launch
    gemm(gh, gl, wqkvh, wqkvl, qkvf, nullptr, nullptr, bqkv,
         NTOK, 3072, HID, HID, HID, 3072, 1.0f, 0, 0);

    // remaining weight transposes (before first use in layer 0)
    transpose_split_kernel<<<dim3(32, 32, 6), tb>>>(wo, woh, wol, HID, HID, HID, HID, 1, 0, HH, HH);
    transpose_split_kernel<<<dim3(86, 32, 6), tb>>>(w1, w13h, w13l, HID, AHID, AHID, HID, 2, 0, HA, F13);
    transpose_split_kernel<<<dim3(86, 32, 6), tb>>>(w3, w13h, w13l, HID, AHID, AHID, HID, 2, 1, HA, F13);
    transpose_split_kernel<<<dim3(32, 86, 6), tb>>>(w2, w2h, w2l, AHID, HID, HID, APAD, 1, 0, HA, (long long)HID*APAD);
    transpose_split_kernel<<<dim3(4, 32, 1),  tb>>>(out_w, outwh, outwl, HID, DIM, DIM, HID, 1, 0, 0, 0);

    for (int l = 0; l < NLAYER; l++) {
        if (l > 0) {
            rmsnorm_kernel<<<NTOK, 256>>>(h, norm1_w + (long long)l*HID, gh, gl);
            gemm(gh, gl, wqkvh + l*QKV, wqkvl + l*QKV, qkvf, nullptr, nullptr, bqkv + (long long)l*3072,
                 NTOK, 3072, HID, HID, HID, 3072, 1.0f, 0, 0);
        }

        rope_apply_kernel<<<(NTOK*NHEAD*32 + 255)/256, 256>>>(qkvf);
        transpose_split_kernel<<<dim3(32, 256, 1), tb>>>(qkvf + 2048, vth, vtl,
                                                         NTOK, HID, 3072, NTOK, 1, 0, 0, 0);

        flash_attn_kernel<<<dim3(4, 256), 256, FA_SMEM>>>(qh, ql, kh, kl, vth, vtl, oh, ol);

        gemm(oh, ol, woh + l*HH, wol + l*HH, h, nullptr, nullptr, bo + (long long)l*HID,
             NTOK, HID, HID, HID, HID, HID, RSCALE, 1, 0);

        rmsnorm_kernel<<<NTOK, 256>>>(h, norm2_w + (long long)l*HID, gh, gl);

        gemm(gh, gl, w13h + l*F13, w13l + l*F13, nullptr, ffh, ffl, b13i + (long long)l*5460,
             NTOK, 5460, HID, HID, HID, APAD, 1.0f, 0, 2);

        gemm(ffh, ffl, w2h + (long long)l*HID*APAD, w2l + (long long)l*HID*APAD, h,
             nullptr, nullptr, b2 + (long long)l*HID,
             NTOK, HID, AHID, APAD, APAD, HID, RSCALE, 1, 0);
    }

    rmsnorm_kernel<<<NTOK, 256>>>(h, onorm_w, gh, gl);
    gemm(gh, gl, outwh, outwl, out, nullptr, nullptr, out_b,
         NTOK, DIM, HID, HID, HID, DIM, 1.0f, 0, 0);
}

// round 16
// speedup vs baseline: 1.6363x; 1.0130x over previous
#include <cuda_runtime.h>
#include <cuda_bf16.h>
#include <cstdint>

#define BATCH   16
#define SEQ     512
#define DIM     128
#define HID     1024
#define NLAYER  6
#define NHEAD   16
#define HEADDIM 64
#define AHID    2730
#define APAD    2736
#define NTOK    8192
#define RSCALE  0.4082482904638630f
#define RMSEPS  1e-6f

#define SPITCH  40                // GEMM smem pitch (80B, conflict-free)

// ---------------------------------------------------------------------------
// Device scratch (allocation-free)
// ---------------------------------------------------------------------------
__device__ __nv_bfloat16 g_winh[131072],       g_winl[131072];
__device__ __nv_bfloat16 g_wqkvh[6*3145728],   g_wqkvl[6*3145728];   // [3072][1024]
__device__ __nv_bfloat16 g_woh [6*1048576],    g_wol [6*1048576];
__device__ __nv_bfloat16 g_w13h[6*5591040],    g_w13l[6*5591040];    // [5460][1024] interleaved w1/w3
__device__ __nv_bfloat16 g_w2h [6*1024*APAD],  g_w2l [6*1024*APAD];  // [1024][APAD]
__device__ __nv_bfloat16 g_outwh[131072],      g_outwl[131072];
__device__ __nv_bfloat16 g_xh [1048576],       g_xl [1048576];
__device__ __nv_bfloat16 g_gh [8388608],       g_gl [8388608];
__device__ __nv_bfloat16 g_qh [8388608],       g_ql [8388608];
__device__ __nv_bfloat16 g_kh [8388608],       g_kl [8388608];
__device__ __nv_bfloat16 g_vh [8388608],       g_vl [8388608];       // [NTOK][HID] natural
__device__ __nv_bfloat16 g_oh [8388608],       g_ol [8388608];
__device__ __nv_bfloat16 g_ffh[(size_t)NTOK*APAD], g_ffl[(size_t)NTOK*APAD];
__device__ float g_h   [8388608];
__device__ float g_qkvf[(size_t)NTOK*3072];
__device__ float g_bqkv[6*3072];
__device__ float g_b13i[6*5460];
__device__ float g_cos [SEQ*32], g_sin[SEQ*32];

// ---------------------------------------------------------------------------
// PTX helpers
// ---------------------------------------------------------------------------
__device__ __forceinline__ void cp_async16(uint32_t dst, const void* src, int srcbytes) {
    asm volatile("cp.async.cg.shared.global [%0], [%1], 16, %2;\n"
                 :: "r"(dst), "l"(src), "r"(srcbytes));
}
#define CP_COMMIT() asm volatile("cp.async.commit_group;\n" ::)
#define CP_WAIT(n)  asm volatile("cp.async.wait_group %0;\n" :: "n"(n))

#define LDSM4(R0,R1,R2,R3,addr)                                               \
  asm volatile("ldmatrix.sync.aligned.m8n8.x4.shared.b16 {%0,%1,%2,%3}, [%4];"\
               : "=r"(R0),"=r"(R1),"=r"(R2),"=r"(R3) : "r"(addr))

#define LDSM4T(R0,R1,R2,R3,addr)                                              \
  asm volatile("ldmatrix.sync.aligned.m8n8.x4.trans.shared.b16 {%0,%1,%2,%3}, [%4];"\
               : "=r"(R0),"=r"(R1),"=r"(R2),"=r"(R3) : "r"(addr))

#define MMA16816(d, A0,A1,A2,A3, B0,B1)                                       \
  asm volatile("mma.sync.aligned.m16n8k16.row.col.f32.bf16.bf16.f32 "         \
               "{%0,%1,%2,%3}, {%4,%5,%6,%7}, {%8,%9}, {%0,%1,%2,%3};"        \
               : "+f"(d[0]), "+f"(d[1]), "+f"(d[2]), "+f"(d[3])               \
               : "r"(A0), "r"(A1), "r"(A2), "r"(A3), "r"(B0), "r"(B1))

__device__ __forceinline__ void split_pack(float x, float y, uint32_t& hi, uint32_t& lo) {
    __nv_bfloat16 hx = __float2bfloat16(x);
    __nv_bfloat16 hy = __float2bfloat16(y);
    __nv_bfloat16 lx = __float2bfloat16(x - __bfloat162float(hx));
    __nv_bfloat16 ly = __float2bfloat16(y - __bfloat162float(hy));
    hi = ((uint32_t)__bfloat16_as_ushort(hy) << 16) | __bfloat16_as_ushort(hx);
    lo = ((uint32_t)__bfloat16_as_ushort(ly) << 16) | __bfloat16_as_ushort(lx);
}

// ---------------------------------------------------------------------------
// Fused flash attention. V loaded in natural [NTOK][HID] layout, transposed
// in-register via ldmatrix.trans for the PV MMA B-operand.
// smem layout unchanged: Qh@0 Ql@9216; stage s @18432+s*18432:
//   Kh +0, Kl +4608, Vh +9216, Vl +13824 (each 64x72 bf16).
// ---------------------------------------------------------------------------
#define FA_SMEM 110592

__global__ void __launch_bounds__(256, 2)
flash_attn_kernel(const __nv_bfloat16* __restrict__ qh_, const __nv_bfloat16* __restrict__ ql_,
                  const __nv_bfloat16* __restrict__ kh_, const __nv_bfloat16* __restrict__ kl_,
                  const __nv_bfloat16* __restrict__ vh_, const __nv_bfloat16* __restrict__ vl_,
                  __nv_bfloat16* __restrict__ oh_, __nv_bfloat16* __restrict__ ol_)
{
    extern __shared__ __nv_bfloat16 sm[];
    uint32_t sb = (uint32_t)__cvta_generic_to_shared(sm);

    const int tid = threadIdx.x, lane = tid & 31, warp = tid >> 5;
    const int g = lane >> 2, t4 = lane & 3;
    const int rr = lane & 15;
    const int chalf = (lane >> 4) << 3;

    const int bh = blockIdx.y;
    const int b = bh >> 4, h = bh & 15;
    const int tok0 = b * SEQ + blockIdx.x * 128;
    const int h64 = h * HEADDIM;

    #pragma unroll
    for (int i = 0; i < 4; i++) {
        int idx = tid + i * 256;
        int r = idx >> 3, ch = idx & 7;
        long long src = (long long)(tok0 + r) * HID + h64 + ch * 8;
        uint32_t d = sb + (uint32_t)(r * 72 + ch * 8) * 2;
        cp_async16(d,           qh_ + src, 16);
        cp_async16(d + 9216*2,  ql_ + src, 16);
    }

    auto loadKV = [&](int stage, int t) {
        uint32_t st = sb + (uint32_t)(18432 + stage * 18432) * 2;
        #pragma unroll
        for (int i = 0; i < 2; i++) {
            int idx = tid + i * 256;
            int r = idx >> 3, ch = idx & 7;
            long long src = (long long)(b * SEQ + t * 64 + r) * HID + h64 + ch * 8;
            uint32_t kd = st + (uint32_t)(r * 72 + ch * 8) * 2;
            cp_async16(kd,            kh_ + src, 16);
            cp_async16(kd + 4608*2,   kl_ + src, 16);
            uint32_t vd = st + (uint32_t)(9216 + r * 72 + ch * 8) * 2;
            cp_async16(vd,            vh_ + src, 16);
            cp_async16(vd + 4608*2,   vl_ + src, 16);
        }
    };

    loadKV(0, 0);
    CP_COMMIT();

    float oacc[8][4];
    #pragma unroll
    for (int nt = 0; nt < 8; nt++)
        #pragma unroll
        for (int e = 0; e < 4; e++) oacc[nt][e] = 0.f;
    float m0 = -1e30f, m1 = -1e30f, l0 = 0.f, l1 = 0.f;

    for (int t = 0; t < 8; t++) {
        CP_WAIT(0);
        __syncthreads();
        if (t + 1 < 8) { loadKV((t + 1) & 1, t + 1); CP_COMMIT(); }

        const uint32_t KHb = 18432u + (uint32_t)(t & 1) * 18432u;
        const uint32_t VHb = KHb + 9216u;

        float sacc[8][4];
        #pragma unroll
        for (int nt = 0; nt < 8; nt++)
            #pragma unroll
            for (int e = 0; e < 4; e++) sacc[nt][e] = 0.f;

        #pragma unroll
        for (int ks = 0; ks < 4; ks++) {
            const int c0 = ks * 16 + chalf;
            uint32_t ah[4], al[4];
            uint32_t ad = sb + (uint32_t)((warp * 16 + rr) * 72 + c0) * 2;
            LDSM4(ah[0], ah[1], ah[2], ah[3], ad);
            LDSM4(al[0], al[1], al[2], al[3], ad + 9216*2);
            uint32_t bh4[8][2], bl4[8][2];
            #pragma unroll
            for (int p = 0; p < 4; p++) {
                uint32_t bd = sb + (uint32_t)(KHb + (p * 16 + rr) * 72 + c0) * 2;
                uint32_t r0, r1, r2, r3;
                LDSM4(r0, r1, r2, r3, bd);
                bh4[2*p][0] = r0; bh4[2*p+1][0] = r1; bh4[2*p][1] = r2; bh4[2*p+1][1] = r3;
                LDSM4(r0, r1, r2, r3, bd + 4608*2);
                bl4[2*p][0] = r0; bl4[2*p+1][0] = r1; bl4[2*p][1] = r2; bl4[2*p+1][1] = r3;
            }
            #pragma unroll
            for (int nt = 0; nt < 8; nt++)
                MMA16816(sacc[nt], ah[0],ah[1],ah[2],ah[3], bh4[nt][0], bh4[nt][1]);
            #pragma unroll
            for (int nt = 0; nt < 8; nt++)
                MMA16816(sacc[nt], ah[0],ah[1],ah[2],ah[3], bl4[nt][0], bl4[nt][1]);
            #pragma unroll
            for (int nt = 0; nt < 8; nt++)
                MMA16816(sacc[nt], al[0],al[1],al[2],al[3], bh4[nt][0], bh4[nt][1]);
        }

        float mx0 = -1e30f, mx1 = -1e30f;
        #pragma unroll
        for (int nt = 0; nt < 8; nt++) {
            sacc[nt][0] *= 0.125f; sacc[nt][1] *= 0.125f;
            sacc[nt][2] *= 0.125f; sacc[nt][3] *= 0.125f;
            mx0 = fmaxf(mx0, fmaxf(sacc[nt][0], sacc[nt][1]));
            mx1 = fmaxf(mx1, fmaxf(sacc[nt][2], sacc[nt][3]));
        }
        mx0 = fmaxf(mx0, __shfl_xor_sync(0xffffffffu, mx0, 1));
        mx0 = fmaxf(mx0, __shfl_xor_sync(0xffffffffu, mx0, 2));
        mx1 = fmaxf(mx1, __shfl_xor_sync(0xffffffffu, mx1, 1));
        mx1 = fmaxf(mx1, __shfl_xor_sync(0xffffffffu, mx1, 2));
        float mn0 = fmaxf(m0, mx0), mn1 = fmaxf(m1, mx1);
        float sc0 = __expf(m0 - mn0), sc1 = __expf(m1 - mn1);
        float rs0 = 0.f, rs1 = 0.f;
        #pragma unroll
        for (int nt = 0; nt < 8; nt++) {
            sacc[nt][0] = __expf(sacc[nt][0] - mn0); rs0 += sacc[nt][0];
            sacc[nt][1] = __expf(sacc[nt][1] - mn0); rs0 += sacc[nt][1];
            sacc[nt][2] = __expf(sacc[nt][2] - mn1); rs1 += sacc[nt][2];
            sacc[nt][3] = __expf(sacc[nt][3] - mn1); rs1 += sacc[nt][3];
        }
        rs0 += __shfl_xor_sync(0xffffffffu, rs0, 1);
        rs0 += __shfl_xor_sync(0xffffffffu, rs0, 2);
        rs1 += __shfl_xor_sync(0xffffffffu, rs1, 1);
        rs1 += __shfl_xor_sync(0xffffffffu, rs1, 2);
        l0 = l0 * sc0 + rs0;  l1 = l1 * sc1 + rs1;
        m0 = mn0;  m1 = mn1;
        #pragma unroll
        for (int nt = 0; nt < 8; nt++) {
            oacc[nt][0] *= sc0; oacc[nt][1] *= sc0;
            oacc[nt][2] *= sc1; oacc[nt][3] *= sc1;
        }

        // O += P V — V tile stored [s][d]; trans-LDSM yields B-frags [d][s]
        #pragma unroll
        for (int j = 0; j < 4; j++) {
            uint32_t aPh[4], aPl[4];
            split_pack(sacc[2*j  ][0], sacc[2*j  ][1], aPh[0], aPl[0]);
            split_pack(sacc[2*j  ][2], sacc[2*j  ][3], aPh[1], aPl[1]);
            split_pack(sacc[2*j+1][0], sacc[2*j+1][1], aPh[2], aPl[2]);
            split_pack(sacc[2*j+1][2], sacc[2*j+1][3], aPh[3], aPl[3]);
            uint32_t bvh[8][2], bvl[8][2];
            #pragma unroll
            for (int p = 0; p < 4; p++) {
                // rows = s (j*16 + rr), col block = (2p + (lane>>4))*8 d-elems
                uint32_t bd = sb + (uint32_t)(VHb + (j*16 + rr) * 72 + (2*p + (lane >> 4)) * 8) * 2;
                uint32_t r0, r1, r2, r3;
                LDSM4T(r0, r1, r2, r3, bd);
                bvh[2*p][0] = r0; bvh[2*p][1] = r1; bvh[2*p+1][0] = r2; bvh[2*p+1][1] = r3;
                LDSM4T(r0, r1, r2, r3, bd + 4608*2);
                bvl[2*p][0] = r0; bvl[2*p][1] = r1; bvl[2*p+1][0] = r2; bvl[2*p+1][1] = r3;
            }
            #pragma unroll
            for (int nt = 0; nt < 8; nt++)
                MMA16816(oacc[nt], aPh[0],aPh[1],aPh[2],aPh[3], bvh[nt][0], bvh[nt][1]);
            #pragma unroll
            for (int nt = 0; nt < 8; nt++)
                MMA16816(oacc[nt], aPl[0],aPl[1],aPl[2],aPl[3], bvh[nt][0], bvh[nt][1]);
            #pragma unroll
            for (int nt = 0; nt < 8; nt++)
                MMA16816(oacc[nt], aPh[0],aPh[1],aPh[2],aPh[3], bvl[nt][0], bvl[nt][1]);
        }
    }

    float inv0 = 1.f / l0, inv1 = 1.f / l1;
    const int row0 = tok0 + warp * 16 + g;
    #pragma unroll
    for (int nt = 0; nt < 8; nt++) {
        int c = h64 + nt * 8 + 2 * t4;
        uint32_t hi, lo;
        split_pack(oacc[nt][0] * inv0, oacc[nt][1] * inv0, hi, lo);
        long long off = (long long)row0 * HID + c;
        *(uint32_t*)(oh_ + off) = hi;
        *(uint32_t*)(ol_ + off) = lo;
        split_pack(oacc[nt][2] * inv1, oacc[nt][3] * inv1, hi, lo);
        off = (long long)(row0 + 8) * HID + c;
        *(uint32_t*)(oh_ + off) = hi;
        *(uint32_t*)(ol_ + off) = lo;
    }
}

// ---------------------------------------------------------------------------
// Pipelined bf16 split GEMM — R13/R15-proven: 256 thr, WR=4 x WC=2, 2 CTA/SM
// ---------------------------------------------------------------------------
template<int NT, int WR, int WC>
__global__ void __launch_bounds__(256, 2)
gemm_mma_kernel(const __nv_bfloat16* __restrict__ Ah, const __nv_bfloat16* __restrict__ Al,
                const __nv_bfloat16* __restrict__ Bh, const __nv_bfloat16* __restrict__ Bl,
                float* __restrict__ C, __nv_bfloat16* __restrict__ Ch, __nv_bfloat16* __restrict__ Cl,
                const float* __restrict__ bias,
                int M, int N, int K, int lda, int ldb, int ldc,
                float alpha, int accum, int outmode)
{
    constexpr int WTM = 128 / WR;
    constexpr int WTN = NT / WC;
    constexpr int MT  = WTM / 16;
    constexpr int NTT = WTN / 8;
    constexpr int NH  = NTT / 4;
    constexpr int APLANE = 128 * SPITCH;
    constexpr int BPLANE = NT * SPITCH;
    constexpr int STAGE_E = 2*APLANE + 2*BPLANE;

    extern __shared__ __nv_bfloat16 smem[];
    uint32_t sbase = (uint32_t)__cvta_generic_to_shared(smem);

    const int tid = threadIdx.x, lane = tid & 31, warp = tid >> 5;
    const int wm = warp / WC, wn = warp % WC;

    const int m0 = blockIdx.y * 128, n0 = blockIdx.x * NT;
    const int T = (K + 31) >> 5;

    auto load_stage = [&](int stg, int k0) {
        uint32_t st = sbase + (uint32_t)stg * (STAGE_E * 2);
        #pragma unroll
        for (int i = 0; i < 2; i++) {
            int idx = tid + i*256;
            int r = idx >> 2, ch = idx & 3;
            int k = k0 + ch*8;
            int s = (K - k) * 2; s = s < 0 ? 0 : (s > 16 ? 16 : s);
            long long aoff = (long long)(m0 + r) * lda + (s ? k : 0);
            uint32_t d = st + (uint32_t)(r*SPITCH + ch*8)*2;
            cp_async16(d,            Ah + aoff, s);
            cp_async16(d + APLANE*2, Al + aoff, s);
        }
        #pragma unroll
        for (int i = 0; i < NT/64; i++) {
            int idx = tid + i*256;
            int r = idx >> 2, ch = idx & 3;
            int n = n0 + r;
            int k = k0 + ch*8;
            int s = (K - k) * 2; s = s < 0 ? 0 : (s > 16 ? 16 : s);
            if (n >= N) s = 0;
            long long boff = (long long)(n < N ? n : 0) * ldb + (s ? k : 0);
            uint32_t d = st + (uint32_t)(2*APLANE + r*SPITCH + ch*8)*2;
            cp_async16(d,            Bh + boff, s);
            cp_async16(d + BPLANE*2, Bl + boff, s);
        }
    };

    load_stage(0, 0);
    CP_COMMIT();

    float acc[MT][NTT][4];
    #pragma unroll
    for (int i = 0; i < MT; i++)
        #pragma unroll
        for (int j = 0; j < NTT; j++)
            #pragma unroll
            for (int e = 0; e < 4; e++) acc[i][j][e] = 0.f;

    for (int kt = 0; kt < T; kt++) {
        CP_WAIT(0);
        __syncthreads();
        if (kt + 1 < T) { load_stage((kt + 1) & 1, (kt + 1) * 32); CP_COMMIT(); }

        uint32_t st = sbase + (uint32_t)((kt & 1) * (STAGE_E * 2));
        #pragma unroll
        for (int ks = 0; ks < 2; ks++) {
            const int c0 = ks*16 + ((lane >> 4) << 3);
            const int rr = lane & 15;
            uint32_t ah[MT][4], al[MT][4];
            #pragma unroll
            for (int mt = 0; mt < MT; mt++) {
                uint32_t ad = st + (uint32_t)(((wm*WTM + mt*16 + rr)*SPITCH + c0)*2);
                LDSM4(ah[mt][0], ah[mt][1], ah[mt][2], ah[mt][3], ad);
                LDSM4(al[mt][0], al[mt][1], al[mt][2], al[mt][3], ad + APLANE*2);
            }
            #pragma unroll
            for (int half = 0; half < NH; half++) {
                uint32_t bh4[4][2], bl4[4][2];
                #pragma unroll
                for (int p = 0; p < 2; p++) {
                    uint32_t bd = st + (uint32_t)((2*APLANE +
                                  (wn*WTN + half*32 + p*16 + rr)*SPITCH + c0)*2);
                    uint32_t r0, r1, r2, r3;
                    LDSM4(r0, r1, r2, r3, bd);
                    bh4[2*p][0] = r0; bh4[2*p+1][0] = r1; bh4[2*p][1] = r2; bh4[2*p+1][1] = r3;
                    LDSM4(r0, r1, r2, r3, bd + BPLANE*2);
                    bl4[2*p][0] = r0; bl4[2*p+1][0] = r1; bl4[2*p][1] = r2; bl4[2*p+1][1] = r3;
                }
                #pragma unroll
                for (int mt = 0; mt < MT; mt++)
                    #pragma unroll
                    for (int j = 0; j < 4; j++)
                        MMA16816(acc[mt][half*4+j], ah[mt][0],ah[mt][1],ah[mt][2],ah[mt][3], bh4[j][0],bh4[j][1]);
                #pragma unroll
                for (int mt = 0; mt < MT; mt++)
                    #pragma unroll
                    for (int j = 0; j < 4; j++)
                        MMA16816(acc[mt][half*4+j], ah[mt][0],ah[mt][1],ah[mt][2],ah[mt][3], bl4[j][0],bl4[j][1]);
                #pragma unroll
                for (int mt = 0; mt < MT; mt++)
                    #pragma unroll
                    for (int j = 0; j < 4; j++)
                        MMA16816(acc[mt][half*4+j], al[mt][0],al[mt][1],al[mt][2],al[mt][3], bh4[j][0],bh4[j][1]);
            }
        }
    }

    const int g = lane >> 2, t4 = lane & 3;
    #pragma unroll
    for (int mt = 0; mt < MT; mt++)
        #pragma unroll
        for (int nt = 0; nt < NTT; nt++) {
            int r = m0 + wm*WTM + mt*16 + g;
            int c = n0 + wn*WTN + nt*8 + 2*t4;
            if (c < N) {
                float bv0 = 0.f, bv1 = 0.f;
                if (bias) { bv0 = bias[c]; bv1 = bias[c+1]; }
                #pragma unroll
                for (int hh = 0; hh < 2; hh++) {
                    int rr = r + hh*8;
                    float v0 = acc[mt][nt][hh*2+0] + bv0;
                    float v1 = acc[mt][nt][hh*2+1] + bv1;
                    if (outmode == 0) {
                        v0 *= alpha; v1 *= alpha;
                        long long off = (long long)rr * ldc + c;
                        float2 o;
                        if (accum) { float2 p = *(const float2*)(C + off); o.x = p.x + v0; o.y = p.y + v1; }
                        else       { o.x = v0; o.y = v1; }
                        *(float2*)(C + off) = o;
                    } else if (outmode == 1) {
                        v0 *= alpha; v1 *= alpha;
                        long long off = (long long)rr * ldc + c;
                        uint32_t ph, pl;
                        split_pack(v0, v1, ph, pl);
                        *(uint32_t*)(Ch + off) = ph;
                        *(uint32_t*)(Cl + off) = pl;
                    } else {
                        float v = v0 / (1.0f + __expf(-v0)) * v1;
                        long long off = (long long)rr * ldc + (c >> 1);
                        __nv_bfloat16 hi = __float2bfloat16(v);
                        Ch[off] = hi;
                        Cl[off] = __float2bfloat16(v - __bfloat162float(hi));
                    }
                }
            }
        }
}

// ---------------------------------------------------------------------------
// Mega-init: one launch does split-x, rope cache, bias prep, in_w transpose,
// and ALL qkv weight transposes. Block ranges:
//  [0,4096)       split x
//  [4096,4160)    rope cache
//  [4160,4232)    concat qkv bias
//  [4232,4296)    interleave b1/b3
//  [4296,4424)    transpose in_w   (bx=local&31, by=local>>5; 32x4)
//  [4424,22856)   transpose qkv    (bx=l&31, by=(l>>5)&31, z=l>>10; 32x32x18)
// ---------------------------------------------------------------------------
__global__ void mega_init_kernel(const float* __restrict__ x,
                                 __nv_bfloat16* __restrict__ xh, __nv_bfloat16* __restrict__ xl,
                                 const float* __restrict__ bq, const float* __restrict__ bk,
                                 const float* __restrict__ bv,
                                 const float* __restrict__ b1, const float* __restrict__ b3,
                                 float* __restrict__ bqkv, float* __restrict__ b13i,
                                 const float* __restrict__ in_w,
                                 __nv_bfloat16* __restrict__ winh, __nv_bfloat16* __restrict__ winl,
                                 const float* __restrict__ wq, const float* __restrict__ wk,
                                 const float* __restrict__ wv,
                                 __nv_bfloat16* __restrict__ wqkvh, __nv_bfloat16* __restrict__ wqkvl)
{
    __shared__ float t[32][33];
    int blk = blockIdx.x, tid = threadIdx.x;
    if (blk < 4096) {
        int i = blk * 256 + tid;
        float v = x[i];
        __nv_bfloat16 hi = __float2bfloat16(v);
        xh[i] = hi;
        xl[i] = __float2bfloat16(v - __bfloat162float(hi));
    } else if (blk < 4160) {
        int i = (blk - 4096) * 256 + tid;
        if (i < SEQ * 32) {
            int s = i >> 5, j = i & 31;
            float invf = expf(-(float)j * (1.0f / 32.0f) * logf(10000.0f));
            float a = (float)s * invf;
            g_cos[i] = cosf(a);
            g_sin[i] = sinf(a);
        }
    } else if (blk < 4232) {
        int i = (blk - 4160) * 256 + tid;
        if (i < NLAYER * 3072) {
            int l = i / 3072, r = i - l * 3072;
            float v;
            if (r < HID)            v = bq[l*HID + r];
            else if (r < 2*HID)     v = bk[l*HID + (r - HID)];
            else                    v = bv[l*HID + (r - 2*HID)];
            bqkv[i] = v;
        }
    } else if (blk < 4296) {
        int i = (blk - 4232) * 256 + tid;
        if (i < NLAYER * AHID) {
            int l = i / AHID, j = i - l * AHID;
            b13i[(long long)l*5460 + 2*j]     = b1[(long long)l*AHID + j];
            b13i[(long long)l*5460 + 2*j + 1] = b3[(long long)l*AHID + j];
        }
    } else if (blk < 4424) {
        // transpose in_w [128][1024] -> planes [1024][128]
        int local = blk - 4296;
        int c0 = (local & 31) * 32, r0 = (local >> 5) * 32;
        int tx = tid & 31, ty = tid >> 5;
        #pragma unroll
        for (int i = ty; i < 32; i += 8)
            t[i][tx] = in_w[(long long)(r0 + i) * HID + c0 + tx];
        __syncthreads();
        #pragma unroll
        for (int i = ty; i < 32; i += 8) {
            float v = t[tx][i];
            __nv_bfloat16 hi = __float2bfloat16(v);
            long long o = (long long)(c0 + i) * DIM + r0 + tx;
            winh[o] = hi;
            winl[o] = __float2bfloat16(v - __bfloat162float(hi));
        }
    } else {
        // transpose qkv weights -> fused planes [3072][1024] per layer
        int l0 = blk - 4424;
        int which = l0 >> 10;               // 0..17 over (3 weights x 6 layers)
        int w3i = which / NLAYER, lay = which % NLAYER;
        const float* src = (w3i == 0 ? wq : w3i == 1 ? wk : wv) + (long long)lay * HID * HID;
        long long dofs = (long long)lay * 3072 * HID + (long long)w3i * HID * HID;
        int c0 = (l0 & 31) * 32, r0 = ((l0 >> 5) & 31) * 32;
        int tx = tid & 31, ty = tid >> 5;
        #pragma unroll
        for (int i = ty; i < 32; i += 8)
            t[i][tx] = src[(long long)(r0 + i) * HID + c0 + tx];
        __syncthreads();
        #pragma unroll
        for (int i = ty; i < 32; i += 8) {
            float v = t[tx][i];
            __nv_bfloat16 hi = __float2bfloat16(v);
            long long o = dofs + (long long)(c0 + i) * HID + r0 + tx;
            wqkvh[o] = hi;
            wqkvl[o] = __float2bfloat16(v - __bfloat162float(hi));
        }
    }
}

__global__ void transpose_split_kernel(const float* __restrict__ src,
                                       __nv_bfloat16* __restrict__ dh,
                                       __nv_bfloat16* __restrict__ dl,
                                       int R, int C, int srcPitch, int dstPitch,
                                       int rowMul, int rowAdd,
                                       long long srcZ, long long dstZ)
{
    __shared__ float t[32][33];
    long long so = (long long)blockIdx.z * srcZ;
    long long dofs = (long long)blockIdx.z * dstZ;
    int c0 = blockIdx.x*32, r0 = blockIdx.y*32;
    #pragma unroll
    for (int i = threadIdx.y; i < 32; i += 8) {
        int r = r0 + i, c = c0 + threadIdx.x;
        t[i][threadIdx.x] = (r < R && c < C) ? src[so + (long long)r*srcPitch + c] : 0.f;
    }
    __syncthreads();
    #pragma unroll
    for (int i = threadIdx.y; i < 32; i += 8) {
        int c = c0 + i, r = r0 + threadIdx.x;
        if (c < C && r < R) {
            float v = t[threadIdx.x][i];
            __nv_bfloat16 hi = __float2bfloat16(v);
            long long o = dofs + (long long)(c*rowMul + rowAdd)*dstPitch + r;
            dh[o] = hi;
            dl[o] = __float2bfloat16(v - __bfloat162float(hi));
        }
    }
}

// vectorized rmsnorm (R15)
__global__ void rmsnorm_kernel(const float* __restrict__ x, const float* __restrict__ w,
                               __nv_bfloat16* __restrict__ oh, __nv_bfloat16* __restrict__ ol)
{
    long long row = blockIdx.x;
    int c = threadIdx.x * 4;
    float4 v4 = *(const float4*)(x + row * HID + c);
    float s = v4.x*v4.x + v4.y*v4.y + v4.z*v4.z + v4.w*v4.w;
    #pragma unroll
    for (int o = 16; o; o >>= 1) s += __shfl_xor_sync(0xffffffffu, s, o);
    __shared__ float red[8];
    int warp = threadIdx.x >> 5, lane = threadIdx.x & 31;
    if (lane == 0) red[warp] = s;
    __syncthreads();
    float tot = red[0]+red[1]+red[2]+red[3]+red[4]+red[5]+red[6]+red[7];
    float inv = rsqrtf(tot * (1.0f / HID) + RMSEPS);
    float4 w4 = *(const float4*)(w + c);
    float a0 = v4.x * inv * w4.x, a1 = v4.y * inv * w4.y;
    float a2 = v4.z * inv * w4.z, a3 = v4.w * inv * w4.w;
    uint32_t h01, l01, h23, l23;
    split_pack(a0, a1, h01, l01);
    split_pack(a2, a3, h23, l23);
    *(uint2*)(oh + row * HID + c) = make_uint2(h01, h23);
    *(uint2*)(ol + row * HID + c) = make_uint2(l01, l23);
}

// rope q,k + split v (natural layout)
__global__ void rope_apply_kernel(const float* __restrict__ qkv)
{
    int i = blockIdx.x * blockDim.x + threadIdx.x;
    if (i >= NTOK * NHEAD * 32) return;
    int m = i >> 9, rem = i & 511;
    int h = rem >> 5, j = rem & 31;
    int s = m & (SEQ - 1);
    float c  = g_cos[s*32 + j];
    float sn = g_sin[s*32 + j];
    long long src = (long long)m * 3072 + h * HEADDIM + j;
    long long dst = (long long)m * HID  + h * HEADDIM + j;
    {
        float a = qkv[src], b = qkv[src + 32];
        float v0 = a * c - b * sn, v1 = b * c + a * sn;
        __nv_bfloat16 h0 = __float2bfloat16(v0), h1 = __float2bfloat16(v1);
        g_qh[dst]      = h0; g_ql[dst]      = __float2bfloat16(v0 - __bfloat162float(h0));
        g_qh[dst + 32] = h1; g_ql[dst + 32] = __float2bfloat16(v1 - __bfloat162float(h1));
    }
    {
        float a = qkv[src + HID], b = qkv[src + HID + 32];
        float v0 = a * c - b * sn, v1 = b * c + a * sn;
        __nv_bfloat16 h0 = __float2bfloat16(v0), h1 = __float2bfloat16(v1);
        g_kh[dst]      = h0; g_kl[dst]      = __float2bfloat16(v0 - __bfloat162float(h0));
        g_kh[dst + 32] = h1; g_kl[dst + 32] = __float2bfloat16(v1 - __bfloat162float(h1));
    }
    {
        float a = qkv[src + 2048], b = qkv[src + 2048 + 32];
        __nv_bfloat16 h0 = __float2bfloat16(a), h1 = __float2bfloat16(b);
        g_vh[dst]      = h0; g_vl[dst]      = __float2bfloat16(a - __bfloat162float(h0));
        g_vh[dst + 32] = h1; g_vl[dst + 32] = __float2bfloat16(b - __bfloat162float(h1));
    }
}

// ---------------------------------------------------------------------------
// Host plumbing
// ---------------------------------------------------------------------------
static inline size_t stage_bytes(int NT) { return (size_t)(2*128*SPITCH + 2*NT*SPITCH) * 2; }

static void gemm(const __nv_bfloat16* Ahp, const __nv_bfloat16* Alp,
                 const __nv_bfloat16* Bhp, const __nv_bfloat16* Blp,
                 float* C, __nv_bfloat16* Ch, __nv_bfloat16* Cl,
                 const float* bias, int M, int N, int K, int lda, int ldb, int ldc,
                 float alpha, int accum, int outmode)
{
    dim3 grid((N + 127) / 128, M / 128, 1);
    size_t sm = 2 * stage_bytes(128);
    gemm_mma_kernel<128,4,2><<<grid, 256, sm>>>(Ahp, Alp, Bhp, Blp, C, Ch, Cl, bias,
        M, N, K, lda, ldb, ldc, alpha, accum, outmode);
}

#define SYM(p, s) cudaGetSymbolAddress((void**)&p, s)

extern "C" void kernel_launch(void* const* d_in, const int* in_sizes, int n_in,
                              void* d_out, int out_size)
{
    const float* x       = (const float*)d_in[0];
    const float* in_w    = (const float*)d_in[1];
    const float* in_b    = (const float*)d_in[2];
    const float* norm1_w = (const float*)d_in[3];
    const float* norm2_w = (const float*)d_in[4];
    const float* wq      = (const float*)d_in[5];
    const float* bq      = (const float*)d_in[6];
    const float* wk      = (const float*)d_in[7];
    const float* bk      = (const float*)d_in[8];
    const float* wv      = (const float*)d_in[9];
    const float* bv      = (const float*)d_in[10];
    const float* wo      = (const float*)d_in[11];
    const float* bo      = (const float*)d_in[12];
    const float* w1      = (const float*)d_in[13];
    const float* b1      = (const float*)d_in[14];
    const float* w3      = (const float*)d_in[15];
    const float* b3      = (const float*)d_in[16];
    const float* w2      = (const float*)d_in[17];
    const float* b2      = (const float*)d_in[18];
    const float* onorm_w = (const float*)d_in[19];
    const float* out_w   = (const float*)d_in[20];
    const float* out_b   = (const float*)d_in[21];
    float* out = (float*)d_out;

    cudaFuncSetAttribute(gemm_mma_kernel<128,4,2>,
        cudaFuncAttributeMaxDynamicSharedMemorySize, (int)(2 * stage_bytes(128)));
    cudaFuncSetAttribute(flash_attn_kernel,
        cudaFuncAttributeMaxDynamicSharedMemorySize, FA_SMEM);

    __nv_bfloat16 *winh,*winl,*wqkvh,*wqkvl,*woh,*wol,*w13h,*w13l,*w2h,*w2l,*outwh,*outwl;
    __nv_bfloat16 *xh,*xl,*gh,*gl,*qh,*ql,*kh,*kl,*vh,*vl,*oh,*ol,*ffh,*ffl;
    float *h,*qkvf,*bqkv,*b13i;
    SYM(winh,g_winh); SYM(winl,g_winl);
    SYM(wqkvh,g_wqkvh); SYM(wqkvl,g_wqkvl);
    SYM(woh,g_woh); SYM(wol,g_wol);
    SYM(w13h,g_w13h); SYM(w13l,g_w13l);
    SYM(w2h,g_w2h); SYM(w2l,g_w2l);
    SYM(outwh,g_outwh); SYM(outwl,g_outwl);
    SYM(xh,g_xh); SYM(xl,g_xl); SYM(gh,g_gh); SYM(gl,g_gl);
    SYM(qh,g_qh); SYM(ql,g_ql); SYM(kh,g_kh); SYM(kl,g_kl);
    SYM(vh,g_vh); SYM(vl,g_vl); SYM(oh,g_oh); SYM(ol,g_ol);
    SYM(ffh,g_ffh); SYM(ffl,g_ffl);
    SYM(h,g_h); SYM(qkvf,g_qkvf);
    SYM(bqkv,g_bqkv); SYM(b13i,g_b13i);

    const long long HH  = (long long)HID*HID;
    const long long HA  = (long long)HID*AHID;
    const long long QKV = (long long)3072*HID;
    const long long F13 = (long long)5460*HID;

    dim3 tb(32, 8);

    // launch #0: mega init (split x, rope cache, biases, in_w + qkv transposes)
    mega_init_kernel<<<22856, 256>>>(x, xh, xl, bq, bk, bv, b1, b3, bqkv, b13i,
                                     in_w, winh, winl, wq, wk, wv, wqkvh, wqkvl);
    // launch #1: in-proj GEMM
    gemm(xh, xl, winh, winl, h, nullptr, nullptr, in_b,
         NTOK, HID, DIM, DIM, DIM, HID, 1.0f, 0, 0);
    // launch #2: rmsnorm layer 0
    rmsnorm_kernel<<<NTOK, 256>>>(h, norm1_w, gh, gl);
    // launch #3: layer-0 QKV GEMM  <-- ncu capture target
    gemm(gh, gl, wqkvh, wqkvl, qkvf, nullptr, nullptr, bqkv,
         NTOK, 3072, HID, HID, HID, 3072, 1.0f, 0, 0);

    // remaining weight transposes
    transpose_split_kernel<<<dim3(32, 32, 6), tb>>>(wo, woh, wol, HID, HID, HID, HID, 1, 0, HH, HH);
    transpose_split_kernel<<<dim3(86, 32, 6), tb>>>(w1, w13h, w13l, HID, AHID, AHID, HID, 2, 0, HA, F13);
    transpose_split_kernel<<<dim3(86, 32, 6), tb>>>(w3, w13h, w13l, HID, AHID, AHID, HID, 2, 1, HA, F13);
    transpose_split_kernel<<<dim3(32, 86, 6), tb>>>(w2, w2h, w2l, AHID, HID, HID, APAD, 1, 0, HA, (long long)HID*APAD);
    transpose_split_kernel<<<dim3(4, 32, 1),  tb>>>(out_w, outwh, outwl, HID, DIM, DIM, HID, 1, 0, 0, 0);

    for (int l = 0; l < NLAYER; l++) {
        if (l > 0) {
            rmsnorm_kernel<<<NTOK, 256>>>(h, norm1_w + (long long)l*HID, gh, gl);
            gemm(gh, gl, wqkvh + l*QKV, wqkvl + l*QKV, qkvf, nullptr, nullptr, bqkv + (long long)l*3072,
                 NTOK, 3072, HID, HID, HID, 3072, 1.0f, 0, 0);
        }

        rope_apply_kernel<<<(NTOK*NHEAD*32 + 255)/256, 256>>>(qkvf);

        flash_attn_kernel<<<dim3(4, 256), 256, FA_SMEM>>>(qh, ql, kh, kl, vh, vl, oh, ol);

        gemm(oh, ol, woh + l*HH, wol + l*HH, h, nullptr, nullptr, bo + (long long)l*HID,
             NTOK, HID, HID, HID, HID, HID, RSCALE, 1, 0);

        rmsnorm_kernel<<<NTOK, 256>>>(h, norm2_w + (long long)l*HID, gh, gl);

        gemm(gh, gl, w13h + l*F13, w13l + l*F13, nullptr, ffh, ffl, b13i + (long long)l*5460,
             NTOK, 5460, HID, HID, HID, APAD, 1.0f, 0, 2);

        gemm(ffh, ffl, w2h + (long long)l*HID*APAD, w2l + (long long)l*HID*APAD, h,
             nullptr, nullptr, b2 + (long long)l*HID,
             NTOK, HID, AHID, APAD, APAD, HID, RSCALE, 1, 0);
    }

    rmsnorm_kernel<<<NTOK, 256>>>(h, onorm_w, gh, gl);
    gemm(gh, gl, outwh, outwl, out, nullptr, nullptr, out_b,
         NTOK, DIM, HID, HID, HID, DIM, 1.0f, 0, 0);
}